// round 11
// baseline (speedup 1.0000x reference)
#include <cuda_runtime.h>
#include <cuda_bf16.h>
#include <math.h>
#include <stdint.h>

#define TT   512
#define BB   64
#define EE   256
#define UU   512
#define G4U  2048
#define NCTA 128   // 64 per direction
#define NTHR 256
#define ZS2  66    // k_rec z stride (floats, even)

// -------- device scratch --------
__device__ __align__(16) float g_Y[(size_t)2 * TT * G4U * BB];   // [dir][t][n][b]
__device__ __align__(16) __nv_bfloat16 g_hT[2][2][2][BB][UU];    // [parity][split][dir][b][u]
__device__ __align__(16) __nv_bfloat16 g_X[TT][2][BB][EE];       // [t][split][b][e]
__device__ __align__(16) __nv_bfloat16 g_Wxb[2][2][G4U][EE];     // [dir][split][n][e]
__device__ unsigned g_flag[2][64][16];                           // 64B-spaced step flags
__device__ unsigned g_cnt[2][32];
__device__ unsigned g_gen[2][32];

__device__ __forceinline__ float sigm(float x) { return 1.0f / (1.0f + expf(-x)); }

__device__ __forceinline__ uint32_t smem_u32(const void* p) {
    uint32_t a;
    asm("{ .reg .u64 t; cvta.to.shared.u64 t, %1; cvt.u32.u64 %0, t; }" : "=r"(a) : "l"(p));
    return a;
}
__device__ __forceinline__ void ldm4(uint32_t* r, uint32_t addr) {
    asm volatile("ldmatrix.sync.aligned.m8n8.x4.shared.b16 {%0,%1,%2,%3}, [%4];"
                 : "=r"(r[0]), "=r"(r[1]), "=r"(r[2]), "=r"(r[3]) : "r"(addr));
}
__device__ __forceinline__ void mma16816(float* d, const uint32_t* a, uint32_t b0, uint32_t b1) {
    asm volatile("mma.sync.aligned.m16n8k16.row.col.f32.bf16.bf16.f32 "
                 "{%0,%1,%2,%3}, {%4,%5,%6,%7}, {%8,%9}, {%0,%1,%2,%3};"
                 : "+f"(d[0]), "+f"(d[1]), "+f"(d[2]), "+f"(d[3])
                 : "r"(a[0]), "r"(a[1]), "r"(a[2]), "r"(a[3]), "r"(b0), "r"(b1));
}
__device__ __forceinline__ void cpasync16(uint32_t dst, const void* src) {
    asm volatile("cp.async.cg.shared.global [%0], [%1], 16;" :: "r"(dst), "l"(src));
}
__device__ __forceinline__ void cpasync_wait() {
    asm volatile("cp.async.commit_group;");
    asm volatile("cp.async.wait_group 0;" ::: "memory");
}

// -------- prep: Wx -> bf16 hi/lo, n-major --------
__global__ __launch_bounds__(256) void k_prepw(const float* __restrict__ Wxf,
                                               const float* __restrict__ Wxb)
{
    int bid = blockIdx.x;
    int dir = bid >> 11, n = bid & 2047;
    const float* Wx = dir ? Wxb : Wxf;
    int e = threadIdx.x;
    float w = Wx[(size_t)e * G4U + n];
    __nv_bfloat16 hi = __float2bfloat16(w);
    __nv_bfloat16 lo = __float2bfloat16(w - __bfloat162float(hi));
    g_Wxb[dir][0][n][e] = hi;
    g_Wxb[dir][1][n][e] = lo;
}

// -------- prep: embedding gather -> bf16 hi/lo --------
__global__ __launch_bounds__(256) void k_prepx(const int* __restrict__ sent,
                                               const float* __restrict__ emb)
{
    int t = blockIdx.x;
    int b0 = blockIdx.y * 16;
    int tid = threadIdx.x;
    __shared__ int vrow[16];
    if (tid < 16) vrow[tid] = sent[(b0 + tid) * TT + t];
    __syncthreads();
    for (int j = 0; j < 16; j++) {
        int b = b0 + j;
        float v = emb[(size_t)vrow[j] * EE + tid];
        __nv_bfloat16 hi = __float2bfloat16(v);
        __nv_bfloat16 lo = __float2bfloat16(v - __bfloat162float(hi));
        g_X[t][0][b][tid] = hi;
        g_X[t][1][b][tid] = lo;
    }
}

// -------- input projection via HMMA (unchanged from R10) --------
__global__ __launch_bounds__(256) void k_xw2(const float* __restrict__ bf,
                                             const float* __restrict__ bbv)
{
    int bid = blockIdx.x;
    int t = bid >> 5;
    int r5 = bid & 31;
    int dir = r5 >> 4, ntile = r5 & 15;

    extern __shared__ char sm[];
    char* smA = sm;
    char* smB = sm + 65536;
    float* zst  = (float*)sm;
    float* zst2 = zst + 128 * 129;

    int tid = threadIdx.x, lane = tid & 31, w = tid >> 5;

    {
        const uint4* Xs = (const uint4*)&g_X[t][0][0][0];
        #pragma unroll
        for (int idx = tid; idx < 4096; idx += 256) {
            int row = idx >> 5, c = idx & 31;
            uint4 v = __ldcg(Xs + idx);
            *(uint4*)(smA + row * 512 + ((c ^ (row & 7)) << 4)) = v;
        }
    }
    {
        const uint4* Ws = (const uint4*)&g_Wxb[dir][0][0][0];
        #pragma unroll
        for (int idx = tid; idx < 8192; idx += 256) {
            int q = idx >> 5, c = idx & 31;
            int sp = q >> 7, nl = q & 127;
            uint4 v = __ldcg(Ws + ((size_t)sp * G4U + ntile * 128 + nl) * 32 + c);
            *(uint4*)(smB + q * 512 + ((c ^ (q & 7)) << 4)) = v;
        }
    }
    __syncthreads();

    uint32_t smA32 = smem_u32(smA), smB32 = smem_u32(smB);
    bool q0w = (w < 4);
    int mg   = q0w ? (w >> 1) : 0;
    int ng   = q0w ? (w & 1) : ((w - 4) >> 1);
    int half = q0w ? 0 : ((w - 4) & 1);
    int arows = mg * 64;
    int brows = (q0w ? 0 : 128) + ng * 64;
    int jlo = half * 8;
    int jn  = q0w ? 16 : 8;

    float D[4][8][4];
    {
        uint32_t aBase[4]; int ar7[4];
        uint32_t bBase[4]; int br7[4];
        int dA = (lane >> 4) & 1, dB = (lane >> 3) & 1;
        #pragma unroll
        for (int mi = 0; mi < 4; mi++) {
            int row = arows + mi * 16 + ((lane >> 3) & 1) * 8 + (lane & 7);
            aBase[mi] = smA32 + row * 512;
            ar7[mi] = row & 7;
        }
        #pragma unroll
        for (int nt = 0; nt < 4; nt++) {
            int row = brows + nt * 16 + ((lane >> 4) & 1) * 8 + (lane & 7);
            bBase[nt] = smB32 + row * 512;
            br7[nt] = row & 7;
        }
        #pragma unroll
        for (int mi = 0; mi < 4; mi++)
            #pragma unroll
            for (int nj = 0; nj < 8; nj++)
                #pragma unroll
                for (int e = 0; e < 4; e++) D[mi][nj][e] = 0.0f;

        #pragma unroll 2
        for (int j = jlo; j < jlo + jn; j++) {
            uint32_t af[4][4], bb[4][4];
            #pragma unroll
            for (int mi = 0; mi < 4; mi++)
                ldm4(af[mi], aBase[mi] + ((((2 * j + dA) ^ ar7[mi])) << 4));
            #pragma unroll
            for (int nt = 0; nt < 4; nt++)
                ldm4(bb[nt], bBase[nt] + ((((2 * j + dB) ^ br7[nt])) << 4));
            #pragma unroll
            for (int mi = 0; mi < 4; mi++)
                #pragma unroll
                for (int nt = 0; nt < 4; nt++) {
                    mma16816(D[mi][2 * nt + 0], af[mi], bb[nt][0], bb[nt][1]);
                    mma16816(D[mi][2 * nt + 1], af[mi], bb[nt][2], bb[nt][3]);
                }
        }
    }
    __syncthreads();

    {
        int g = lane >> 2, tq = lane & 3;
        float* dst = q0w ? zst : zst2;
        int zrb = q0w ? arows : half * 64;
        #pragma unroll
        for (int mi = 0; mi < 4; mi++)
            #pragma unroll
            for (int nj = 0; nj < 8; nj++) {
                int r = zrb + mi * 16 + g;
                int c = ng * 64 + nj * 8 + 2 * tq;
                dst[r * 129 + c]           = D[mi][nj][0];
                dst[r * 129 + c + 1]       = D[mi][nj][1];
                dst[(r + 8) * 129 + c]     = D[mi][nj][2];
                dst[(r + 8) * 129 + c + 1] = D[mi][nj][3];
            }
    }
    __syncthreads();

    {
        const float* bias = dir ? bbv : bf;
        float* Y = g_Y + ((size_t)dir * TT + t) * (size_t)(G4U * BB)
                       + (size_t)ntile * 128 * BB;
        #pragma unroll
        for (int rep = 0; rep < 8; rep++) {
            int task = tid + 256 * rep;
            int n = task >> 4, b4 = (task & 15) << 2;
            float bn = bias[ntile * 128 + n];
            float4 o;
            o.x = zst[(b4 + 0) * 129 + n] + zst[(b4 + 64) * 129 + n]
                + zst2[(b4 + 0) * 129 + n] + zst2[(b4 + 64) * 129 + n] + bn;
            o.y = zst[(b4 + 1) * 129 + n] + zst[(b4 + 65) * 129 + n]
                + zst2[(b4 + 1) * 129 + n] + zst2[(b4 + 65) * 129 + n] + bn;
            o.z = zst[(b4 + 2) * 129 + n] + zst[(b4 + 66) * 129 + n]
                + zst2[(b4 + 2) * 129 + n] + zst2[(b4 + 66) * 129 + n] + bn;
            o.w = zst[(b4 + 3) * 129 + n] + zst[(b4 + 67) * 129 + n]
                + zst2[(b4 + 3) * 129 + n] + zst2[(b4 + 67) * 129 + n] + bn;
            *(float4*)(Y + (size_t)n * BB + b4) = o;
        }
    }
}

// -------- persistent HMMA recurrence: m64n32 warps, 2-phase z, split barrier --------
// w0: A rows 0-63  x W_hi, K-half0   -> zst[0-63][0-31]   (phase1)
// w1: A rows 64-127x W_hi, K-half0   -> zst[64-127][0-31] (phase1)
// w2: A rows 0-63  x W_hi, K-half1   -> += zst[0-63][0-31]   (phase2)
// w3: A rows 64-127x W_hi, K-half1   -> += zst[64-127][0-31] (phase2)
// w4: A_hi x W_lo, K-q0 -> zst[0-63][32-63]    (phase1)
// w5: A_hi x W_lo, K-q1 -> zst[64-127][32-63]  (phase1)
// w6: A_hi x W_lo, K-q2 -> += zst[0-63][32-63]   (phase2)
// w7: A_hi x W_lo, K-q3 -> += zst[64-127][32-63] (phase2)
__global__ __launch_bounds__(NTHR, 1) void k_rec(
    const float* __restrict__ Whf, const float* __restrict__ Whb)
{
    extern __shared__ char dsm[];
    char* smA  = dsm;                        // 131072 B
    char* smB  = dsm + 131072;               // 65536 B
    float* zst = (float*)(dsm + 131072 + 65536);   // [128][ZS2]
    __nv_bfloat16* hstage = (__nv_bfloat16*)smA;

    int tid = threadIdx.x, lane = tid & 31, w = tid >> 5;
    int dir = blockIdx.x >> 6;
    int cta = blockIdx.x & 63;
    int u0  = cta * 8;
    const float* Wh = dir ? Whb : Whf;

    // B build (once): rows 0-31 W_hi, 32-63 W_lo
    for (int idx = tid; idx < 64 * 512; idx += NTHR) {
        int n = idx >> 9, k = idx & 511;
        int nl = n & 31;
        float wv = Wh[(size_t)k * G4U + ((nl >> 3) * UU + u0 + (nl & 7))];
        __nv_bfloat16 hi = __float2bfloat16(wv);
        __nv_bfloat16 v = (n < 32) ? hi : __float2bfloat16(wv - __bfloat162float(hi));
        uint32_t off = (uint32_t)(n * 1024 + ((((k >> 3) ^ (n & 7))) << 4) + (k & 7) * 2);
        *(__nv_bfloat16*)(smB + off) = v;
    }
    for (int i = tid; i < 128 * ZS2; i += NTHR) zst[i] = 0.0f;

    // warp tiling (m64n32 tiles, balanced: SMSP_i = 256+128 HMMA)
    uint32_t smA32 = smem_u32(smA), smB32 = smem_u32(smB);
    bool q0w = (w < 4);
    int arow  = q0w ? ((w & 1) * 64) : 0;
    int qlo   = q0w ? ((w >> 1) * 4) : ((w - 4) * 2);
    int qn    = q0w ? 4 : 2;
    int nbase = q0w ? 0 : 32;
    int zrow  = q0w ? arow : (((w - 4) & 1) * 64);
    int zcol  = q0w ? 0 : 32;
    bool phase1 = q0w ? (w < 2) : (w < 6);

    uint32_t aBase[4], bBase[2], aSw[4][4], bSw[2][4];
    {
        int dA = (lane >> 4) & 1;
        #pragma unroll
        for (int mt = 0; mt < 4; mt++) {
            int row = arow + mt * 16 + ((lane >> 3) & 1) * 8 + (lane & 7);
            aBase[mt] = smA32 + row * 1024;
            #pragma unroll
            for (int j = 0; j < 4; j++)
                aSw[mt][j] = (uint32_t)(((2 * j + dA) ^ (row & 7)) << 4);
        }
        int dB = (lane >> 3) & 1;
        #pragma unroll
        for (int nt = 0; nt < 2; nt++) {
            int row = nbase + nt * 16 + ((lane >> 4) & 1) * 8 + (lane & 7);
            bBase[nt] = smB32 + row * 1024;
            #pragma unroll
            for (int j = 0; j < 4; j++)
                bSw[nt][j] = (uint32_t)(((2 * j + dB) ^ (row & 7)) << 4);
        }
    }

    int b = tid & 63, du0 = tid >> 6;
    float creg[2] = {0.0f, 0.0f};
    const float* Ybase = g_Y + (size_t)dir * TT * (size_t)(G4U * BB);
    __syncthreads();

    for (int t = 0; t < TT; t++) {
        // Y prefetch for this step (issues before barrier wait -> latency hidden)
        int ttv = dir ? (TT - 1 - t) : t;
        const float* Yt = Ybase + (size_t)ttv * (size_t)(G4U * BB);
        float yv[8];
        #pragma unroll
        for (int g = 0; g < 4; g++) {
            yv[g]     = __ldcg(Yt + (size_t)(g * UU + u0 + du0) * BB + b);
            yv[4 + g] = __ldcg(Yt + (size_t)(g * UU + u0 + du0 + 4) * BB + b);
        }

        if (t > 0) {
            // barrier WAIT (arrive happened at end of previous step)
            if (tid < 64) {
                while (*(volatile unsigned*)&g_flag[dir][tid][0] < (unsigned)t) {}
            }
            __syncthreads();

            {   // A build via cp.async (gmem -> smem direct)
                const __nv_bfloat16* hp = &g_hT[t & 1][0][dir][0][0];
                const size_t split_stride = (size_t)2 * BB * UU;
                #pragma unroll 8
                for (int rep = 0; rep < 32; rep++) {
                    int idx = tid + NTHR * rep;
                    int row = idx >> 6, c = idx & 63;
                    int sp = row >> 6, br = row & 63;
                    const void* src = hp + (size_t)sp * split_stride + (size_t)br * UU + c * 8;
                    cpasync16(smA32 + row * 1024 + ((c ^ (row & 7)) << 4), src);
                }
                cpasync_wait();
            }
            __syncthreads();

            {
                float D[4][4][4];
                #pragma unroll
                for (int mi = 0; mi < 4; mi++)
                    #pragma unroll
                    for (int nj = 0; nj < 4; nj++)
                        #pragma unroll
                        for (int e = 0; e < 4; e++) D[mi][nj][e] = 0.0f;

                for (int q = qlo; q < qlo + qn; q++) {
                    uint32_t qo = (uint32_t)(q * 128);
                    #pragma unroll
                    for (int j = 0; j < 4; j++) {
                        uint32_t af[4][4], p0[4], p1[4];
                        #pragma unroll
                        for (int mi = 0; mi < 4; mi++)
                            ldm4(af[mi], aBase[mi] + qo + aSw[mi][j]);
                        ldm4(p0, bBase[0] + qo + bSw[0][j]);
                        ldm4(p1, bBase[1] + qo + bSw[1][j]);
                        #pragma unroll
                        for (int mi = 0; mi < 4; mi++) {
                            mma16816(D[mi][0], af[mi], p0[0], p0[1]);
                            mma16816(D[mi][1], af[mi], p0[2], p0[3]);
                            mma16816(D[mi][2], af[mi], p1[0], p1[1]);
                            mma16816(D[mi][3], af[mi], p1[2], p1[3]);
                        }
                    }
                }

                int g = lane >> 2, tq = lane & 3;
                if (phase1) {
                    #pragma unroll
                    for (int mi = 0; mi < 4; mi++) {
                        int r0_ = zrow + mi * 16 + g;
                        int cc = zcol + 2 * tq;
                        #pragma unroll
                        for (int nj = 0; nj < 4; nj++) {
                            *(float2*)(zst + r0_ * ZS2 + cc + nj * 8) =
                                make_float2(D[mi][nj][0], D[mi][nj][1]);
                            *(float2*)(zst + (r0_ + 8) * ZS2 + cc + nj * 8) =
                                make_float2(D[mi][nj][2], D[mi][nj][3]);
                        }
                    }
                }
                __syncthreads();
                if (!phase1) {
                    #pragma unroll
                    for (int mi = 0; mi < 4; mi++) {
                        int r0_ = zrow + mi * 16 + g;
                        int cc = zcol + 2 * tq;
                        #pragma unroll
                        for (int nj = 0; nj < 4; nj++) {
                            float2* p = (float2*)(zst + r0_ * ZS2 + cc + nj * 8);
                            float2 v = *p;
                            *p = make_float2(v.x + D[mi][nj][0], v.y + D[mi][nj][1]);
                            float2* p2 = (float2*)(zst + (r0_ + 8) * ZS2 + cc + nj * 8);
                            float2 v2 = *p2;
                            *p2 = make_float2(v2.x + D[mi][nj][2], v2.y + D[mi][nj][3]);
                        }
                    }
                }
            }
        }
        __syncthreads();

        {   // cell update: z = Q0(hi@b + lo@64+b) + Q1(q02@b + q13@64+b) + Y
            #pragma unroll
            for (int cell = 0; cell < 2; cell++) {
                int du = du0 + 4 * cell;
                float zg4[4];
                #pragma unroll
                for (int g = 0; g < 4; g++) {
                    int lc = g * 8 + du;
                    zg4[g] = zst[b * ZS2 + lc] + zst[(64 + b) * ZS2 + lc]
                           + zst[b * ZS2 + 32 + lc] + zst[(64 + b) * ZS2 + 32 + lc]
                           + yv[cell * 4 + g];
                }
                float cn = sigm(zg4[1]) * creg[cell] + sigm(zg4[0]) * tanhf(zg4[2]);
                float hn = sigm(zg4[3]) * tanhf(cn);
                creg[cell] = cn;
                __nv_bfloat16 hi = __float2bfloat16(hn);
                __nv_bfloat16 lo = __float2bfloat16(hn - __bfloat162float(hi));
                hstage[(0 * 64 + b) * 8 + du] = hi;
                hstage[(1 * 64 + b) * 8 + du] = lo;
            }
        }
        __syncthreads();

        if (tid < 128) {
            int sp = tid >> 6, br = tid & 63;
            uint4 v = *(const uint4*)(hstage + (sp * 64 + br) * 8);
            *(uint4*)(&g_hT[(t + 1) & 1][sp][dir][br][u0]) = v;
        }

        // barrier ARRIVE
        if (t < TT - 1) {
            __threadfence();
            __syncthreads();
            if (tid == 0) *(volatile unsigned*)&g_flag[dir][cta][0] = (unsigned)(t + 1);
        }
    }

    // final all-arrive barrier, then flag reset for graph replay
    __threadfence();
    __syncthreads();
    if (tid == 0) {
        volatile unsigned* gen = &g_gen[dir][0];
        unsigned g = *gen;
        unsigned a = atomicAdd(&g_cnt[dir][0], 1u);
        if (a == 63) {
            g_cnt[dir][0] = 0;
            __threadfence();
            *gen = g + 1;
        } else {
            while (*gen == g) {}
        }
        g_flag[dir][cta][0] = 0;
    }
}

// -------- head --------
__global__ __launch_bounds__(256) void k_head(
    const float* __restrict__ W1, const float* __restrict__ b1,
    const float* __restrict__ W2, const float* __restrict__ b2,
    float* __restrict__ out)
{
    int b = blockIdx.x;
    int tid = threadIdx.x;
    int j = tid & 63, kq = tid >> 6;
    float s = 0.0f;
    for (int k = kq * 256; k < kq * 256 + 256; k++) {
        int dir = k >> 9, u = k & 511;
        float hv = __bfloat162float(g_hT[0][0][dir][b][u]) +
                   __bfloat162float(g_hT[0][1][dir][b][u]);
        s += hv * W1[(size_t)k * 64 + j];
    }
    __shared__ float red[4][64];
    red[kq][j] = s;
    __syncthreads();
    if (tid < 64) {
        float sj = red[0][j] + red[1][j] + red[2][j] + red[3][j] + b1[j];
        red[0][j] = sj * W2[j];
    }
    __syncthreads();
    if (tid == 0) {
        float v = 0.0f;
        #pragma unroll
        for (int q = 0; q < 64; q++) v += red[0][q];
        out[b] = sigm(v + b2[0]);
    }
}

extern "C" void kernel_launch(void* const* d_in, const int* in_sizes, int n_in,
                              void* d_out, int out_size)
{
    const int*   sent = (const int*)  d_in[0];
    const float* emb  = (const float*)d_in[1];
    const float* Wxf  = (const float*)d_in[2];
    const float* Whf  = (const float*)d_in[3];
    const float* bf   = (const float*)d_in[4];
    const float* Wxb  = (const float*)d_in[5];
    const float* Whb  = (const float*)d_in[6];
    const float* bbv  = (const float*)d_in[7];
    const float* W1   = (const float*)d_in[8];
    const float* b1   = (const float*)d_in[9];
    const float* W2   = (const float*)d_in[10];
    const float* b2   = (const float*)d_in[11];
    float* out = (float*)d_out;

    const int smem_rec = 131072 + 65536 + 128 * ZS2 * 4;   // 230400 B
    const int smem_xw  = 65536 + 131072;                   // 196608 B
    cudaFuncSetAttribute(k_rec, cudaFuncAttributeMaxDynamicSharedMemorySize, smem_rec);
    cudaFuncSetAttribute(k_xw2, cudaFuncAttributeMaxDynamicSharedMemorySize, smem_xw);

    k_prepw<<<4096, 256>>>(Wxf, Wxb);
    k_prepx<<<dim3(512, 4), 256>>>(sent, emb);
    k_xw2<<<512 * 32, 256, smem_xw>>>(bf, bbv);
    k_rec<<<NCTA, NTHR, smem_rec>>>(Whf, Whb);
    k_head<<<64, 256>>>(W1, b1, W2, b2, out);
}

// round 12
// speedup vs baseline: 1.1527x; 1.1527x over previous
#include <cuda_runtime.h>
#include <cuda_bf16.h>
#include <math.h>
#include <stdint.h>

#define TT   512
#define BB   64
#define EE   256
#define UU   512
#define G4U  2048
#define NCTA 128   // 64 per direction
#define NTHR 256
#define ZS2  66    // k_rec z stride (floats, even)

// -------- device scratch --------
__device__ __align__(16) float g_Y[(size_t)2 * TT * G4U * BB];   // [dir][t][n][b]
__device__ __align__(16) __nv_bfloat16 g_hT[2][2][2][BB][UU];    // [parity][split][dir][b][u]
__device__ __align__(16) __nv_bfloat16 g_X[TT][2][BB][EE];       // [t][split][b][e]
__device__ __align__(16) __nv_bfloat16 g_Wxb[2][2][G4U][EE];     // [dir][split][n][e]
__device__ unsigned g_flag[2][64][16];                           // 64B-spaced step flags
__device__ unsigned g_cnt[2][32];
__device__ unsigned g_gen[2][32];

__device__ __forceinline__ float sigm(float x) { return 1.0f / (1.0f + expf(-x)); }

__device__ __forceinline__ uint32_t smem_u32(const void* p) {
    uint32_t a;
    asm("{ .reg .u64 t; cvta.to.shared.u64 t, %1; cvt.u32.u64 %0, t; }" : "=r"(a) : "l"(p));
    return a;
}
__device__ __forceinline__ void ldm4(uint32_t* r, uint32_t addr) {
    asm volatile("ldmatrix.sync.aligned.m8n8.x4.shared.b16 {%0,%1,%2,%3}, [%4];"
                 : "=r"(r[0]), "=r"(r[1]), "=r"(r[2]), "=r"(r[3]) : "r"(addr));
}
__device__ __forceinline__ void mma16816(float* d, const uint32_t* a, uint32_t b0, uint32_t b1) {
    asm volatile("mma.sync.aligned.m16n8k16.row.col.f32.bf16.bf16.f32 "
                 "{%0,%1,%2,%3}, {%4,%5,%6,%7}, {%8,%9}, {%0,%1,%2,%3};"
                 : "+f"(d[0]), "+f"(d[1]), "+f"(d[2]), "+f"(d[3])
                 : "r"(a[0]), "r"(a[1]), "r"(a[2]), "r"(a[3]), "r"(b0), "r"(b1));
}
__device__ __forceinline__ void cpasync16(uint32_t dst, const void* src) {
    asm volatile("cp.async.cg.shared.global [%0], [%1], 16;" :: "r"(dst), "l"(src));
}
__device__ __forceinline__ void cp_commit() {
    asm volatile("cp.async.commit_group;");
}
__device__ __forceinline__ void cp_wait1() {
    asm volatile("cp.async.wait_group 1;" ::: "memory");
}
__device__ __forceinline__ void cp_wait0() {
    asm volatile("cp.async.wait_group 0;" ::: "memory");
}

// -------- prep: Wx -> bf16 hi/lo, n-major --------
__global__ __launch_bounds__(256) void k_prepw(const float* __restrict__ Wxf,
                                               const float* __restrict__ Wxb)
{
    int bid = blockIdx.x;
    int dir = bid >> 11, n = bid & 2047;
    const float* Wx = dir ? Wxb : Wxf;
    int e = threadIdx.x;
    float w = Wx[(size_t)e * G4U + n];
    __nv_bfloat16 hi = __float2bfloat16(w);
    __nv_bfloat16 lo = __float2bfloat16(w - __bfloat162float(hi));
    g_Wxb[dir][0][n][e] = hi;
    g_Wxb[dir][1][n][e] = lo;
}

// -------- prep: embedding gather -> bf16 hi/lo --------
__global__ __launch_bounds__(256) void k_prepx(const int* __restrict__ sent,
                                               const float* __restrict__ emb)
{
    int t = blockIdx.x;
    int b0 = blockIdx.y * 16;
    int tid = threadIdx.x;
    __shared__ int vrow[16];
    if (tid < 16) vrow[tid] = sent[(b0 + tid) * TT + t];
    __syncthreads();
    for (int j = 0; j < 16; j++) {
        int b = b0 + j;
        float v = emb[(size_t)vrow[j] * EE + tid];
        __nv_bfloat16 hi = __float2bfloat16(v);
        __nv_bfloat16 lo = __float2bfloat16(v - __bfloat162float(hi));
        g_X[t][0][b][tid] = hi;
        g_X[t][1][b][tid] = lo;
    }
}

// -------- input projection via HMMA (R10, unchanged) --------
__global__ __launch_bounds__(256) void k_xw2(const float* __restrict__ bf,
                                             const float* __restrict__ bbv)
{
    int bid = blockIdx.x;
    int t = bid >> 5;
    int r5 = bid & 31;
    int dir = r5 >> 4, ntile = r5 & 15;

    extern __shared__ char sm[];
    char* smA = sm;
    char* smB = sm + 65536;
    float* zst  = (float*)sm;
    float* zst2 = zst + 128 * 129;

    int tid = threadIdx.x, lane = tid & 31, w = tid >> 5;

    {
        const uint4* Xs = (const uint4*)&g_X[t][0][0][0];
        #pragma unroll
        for (int idx = tid; idx < 4096; idx += 256) {
            int row = idx >> 5, c = idx & 31;
            uint4 v = __ldcg(Xs + idx);
            *(uint4*)(smA + row * 512 + ((c ^ (row & 7)) << 4)) = v;
        }
    }
    {
        const uint4* Ws = (const uint4*)&g_Wxb[dir][0][0][0];
        #pragma unroll
        for (int idx = tid; idx < 8192; idx += 256) {
            int q = idx >> 5, c = idx & 31;
            int sp = q >> 7, nl = q & 127;
            uint4 v = __ldcg(Ws + ((size_t)sp * G4U + ntile * 128 + nl) * 32 + c);
            *(uint4*)(smB + q * 512 + ((c ^ (q & 7)) << 4)) = v;
        }
    }
    __syncthreads();

    uint32_t smA32 = smem_u32(smA), smB32 = smem_u32(smB);
    bool q0w = (w < 4);
    int mg   = q0w ? (w >> 1) : 0;
    int ng   = q0w ? (w & 1) : ((w - 4) >> 1);
    int half = q0w ? 0 : ((w - 4) & 1);
    int arows = mg * 64;
    int brows = (q0w ? 0 : 128) + ng * 64;
    int jlo = half * 8;
    int jn  = q0w ? 16 : 8;

    float D[4][8][4];
    {
        uint32_t aBase[4]; int ar7[4];
        uint32_t bBase[4]; int br7[4];
        int dA = (lane >> 4) & 1, dB = (lane >> 3) & 1;
        #pragma unroll
        for (int mi = 0; mi < 4; mi++) {
            int row = arows + mi * 16 + ((lane >> 3) & 1) * 8 + (lane & 7);
            aBase[mi] = smA32 + row * 512;
            ar7[mi] = row & 7;
        }
        #pragma unroll
        for (int nt = 0; nt < 4; nt++) {
            int row = brows + nt * 16 + ((lane >> 4) & 1) * 8 + (lane & 7);
            bBase[nt] = smB32 + row * 512;
            br7[nt] = row & 7;
        }
        #pragma unroll
        for (int mi = 0; mi < 4; mi++)
            #pragma unroll
            for (int nj = 0; nj < 8; nj++)
                #pragma unroll
                for (int e = 0; e < 4; e++) D[mi][nj][e] = 0.0f;

        #pragma unroll 2
        for (int j = jlo; j < jlo + jn; j++) {
            uint32_t af[4][4], bb[4][4];
            #pragma unroll
            for (int mi = 0; mi < 4; mi++)
                ldm4(af[mi], aBase[mi] + ((((2 * j + dA) ^ ar7[mi])) << 4));
            #pragma unroll
            for (int nt = 0; nt < 4; nt++)
                ldm4(bb[nt], bBase[nt] + ((((2 * j + dB) ^ br7[nt])) << 4));
            #pragma unroll
            for (int mi = 0; mi < 4; mi++)
                #pragma unroll
                for (int nt = 0; nt < 4; nt++) {
                    mma16816(D[mi][2 * nt + 0], af[mi], bb[nt][0], bb[nt][1]);
                    mma16816(D[mi][2 * nt + 1], af[mi], bb[nt][2], bb[nt][3]);
                }
        }
    }
    __syncthreads();

    {
        int g = lane >> 2, tq = lane & 3;
        float* dst = q0w ? zst : zst2;
        int zrb = q0w ? arows : half * 64;
        #pragma unroll
        for (int mi = 0; mi < 4; mi++)
            #pragma unroll
            for (int nj = 0; nj < 8; nj++) {
                int r = zrb + mi * 16 + g;
                int c = ng * 64 + nj * 8 + 2 * tq;
                dst[r * 129 + c]           = D[mi][nj][0];
                dst[r * 129 + c + 1]       = D[mi][nj][1];
                dst[(r + 8) * 129 + c]     = D[mi][nj][2];
                dst[(r + 8) * 129 + c + 1] = D[mi][nj][3];
            }
    }
    __syncthreads();

    {
        const float* bias = dir ? bbv : bf;
        float* Y = g_Y + ((size_t)dir * TT + t) * (size_t)(G4U * BB)
                       + (size_t)ntile * 128 * BB;
        #pragma unroll
        for (int rep = 0; rep < 8; rep++) {
            int task = tid + 256 * rep;
            int n = task >> 4, b4 = (task & 15) << 2;
            float bn = bias[ntile * 128 + n];
            float4 o;
            o.x = zst[(b4 + 0) * 129 + n] + zst[(b4 + 64) * 129 + n]
                + zst2[(b4 + 0) * 129 + n] + zst2[(b4 + 64) * 129 + n] + bn;
            o.y = zst[(b4 + 1) * 129 + n] + zst[(b4 + 65) * 129 + n]
                + zst2[(b4 + 1) * 129 + n] + zst2[(b4 + 65) * 129 + n] + bn;
            o.z = zst[(b4 + 2) * 129 + n] + zst[(b4 + 66) * 129 + n]
                + zst2[(b4 + 2) * 129 + n] + zst2[(b4 + 66) * 129 + n] + bn;
            o.w = zst[(b4 + 3) * 129 + n] + zst[(b4 + 67) * 129 + n]
                + zst2[(b4 + 3) * 129 + n] + zst2[(b4 + 67) * 129 + n] + bn;
            *(float4*)(Y + (size_t)n * BB + b4) = o;
        }
    }
}

// -------- persistent HMMA recurrence: R10 tiling + 2-group cp.async pipeline --------
// Tiles: w0-3: Q0 (A rows w*32..+32 x W_hi, K split into halves across phases)
//        w4,w5: Q1 K-half0 (phase A); w6,w7: Q1 K-half1 (phase B)
__global__ __launch_bounds__(NTHR, 1) void k_rec(
    const float* __restrict__ Whf, const float* __restrict__ Whb)
{
    extern __shared__ char dsm[];
    char* smA  = dsm;                        // 131072 B
    char* smB  = dsm + 131072;               // 65536 B
    float* zst = (float*)(dsm + 131072 + 65536);   // [128][ZS2]
    __nv_bfloat16* hstage = (__nv_bfloat16*)smA;

    int tid = threadIdx.x, lane = tid & 31, w = tid >> 5;
    int dir = blockIdx.x >> 6;
    int cta = blockIdx.x & 63;
    int u0  = cta * 8;
    const float* Wh = dir ? Whb : Whf;

    // B build (once): rows 0-31 W_hi, 32-63 W_lo
    for (int idx = tid; idx < 64 * 512; idx += NTHR) {
        int n = idx >> 9, k = idx & 511;
        int nl = n & 31;
        float wv = Wh[(size_t)k * G4U + ((nl >> 3) * UU + u0 + (nl & 7))];
        __nv_bfloat16 hi = __float2bfloat16(wv);
        __nv_bfloat16 v = (n < 32) ? hi : __float2bfloat16(wv - __bfloat162float(hi));
        uint32_t off = (uint32_t)(n * 1024 + ((((k >> 3) ^ (n & 7))) << 4) + (k & 7) * 2);
        *(__nv_bfloat16*)(smB + off) = v;
    }
    for (int i = tid; i < 128 * ZS2; i += NTHR) zst[i] = 0.0f;

    // warp tiling (R10): all 8 warps, per-SMSP balanced (384 HMMA each)
    uint32_t smA32 = smem_u32(smA), smB32 = smem_u32(smB);
    bool q0w = (w < 4);
    int w4 = w - 4;
    int arow  = q0w ? (w * 32) : ((w4 >> 1) * 32);
    int nbase = q0w ? 0 : 32;
    int half  = q0w ? 0 : (w4 & 1);
    int zrow  = q0w ? arow : (arow + 64 * half);
    int zcol  = q0w ? 0 : 32;
    // phase schedule: w0-3 split q0-3 / q4-7; w4,w5 all in phase A; w6,w7 all in phase B
    int qloA = q0w ? 0 : (w4 & 1) * 4;           // w4 -> q0-3? no: w4 qlo=0, w5 qlo... see qnA
    int qnA, qloB, qnB;
    if (q0w) { qloA = 0; qnA = 4; qloB = 4; qnB = 4; }
    else if (w == 4) { qloA = 0; qnA = 2; qloB = 0; qnB = 0; }
    else if (w == 5) { qloA = 2; qnA = 2; qloB = 0; qnB = 0; }
    else if (w == 6) { qloA = 0; qnA = 0; qloB = 4; qnB = 2; }
    else             { qloA = 0; qnA = 0; qloB = 6; qnB = 2; }

    uint32_t aBase[2], bBase[2], aSw[2][4], bSw[2][4];
    {
        int dA = (lane >> 4) & 1;
        #pragma unroll
        for (int mt = 0; mt < 2; mt++) {
            int row = arow + mt * 16 + ((lane >> 3) & 1) * 8 + (lane & 7);
            aBase[mt] = smA32 + row * 1024;
            #pragma unroll
            for (int j = 0; j < 4; j++)
                aSw[mt][j] = (uint32_t)(((2 * j + dA) ^ (row & 7)) << 4);
        }
        int dB = (lane >> 3) & 1;
        #pragma unroll
        for (int nt = 0; nt < 2; nt++) {
            int row = nbase + nt * 16 + ((lane >> 4) & 1) * 8 + (lane & 7);
            bBase[nt] = smB32 + row * 1024;
            #pragma unroll
            for (int j = 0; j < 4; j++)
                bSw[nt][j] = (uint32_t)(((2 * j + dB) ^ (row & 7)) << 4);
        }
    }

    int b = tid & 63, du0 = tid >> 6;
    float creg[2] = {0.0f, 0.0f};
    const float* Ybase = g_Y + (size_t)dir * TT * (size_t)(G4U * BB);
    __syncthreads();

    for (int t = 0; t < TT; t++) {
        int ttv = dir ? (TT - 1 - t) : t;
        const float* Yt = Ybase + (size_t)ttv * (size_t)(G4U * BB);
        float yv[8];
        #pragma unroll
        for (int g = 0; g < 4; g++) {
            yv[g]     = __ldcg(Yt + (size_t)(g * UU + u0 + du0) * BB + b);
            yv[4 + g] = __ldcg(Yt + (size_t)(g * UU + u0 + du0 + 4) * BB + b);
        }

        if (t > 0) {
            // barrier wait for producers of h(t)
            if (tid < 64) {
                while (*(volatile unsigned*)&g_flag[dir][tid][0] < (unsigned)t) {}
            }
            __syncthreads();

            // A build via cp.async: 2 K-half groups
            {
                const __nv_bfloat16* hp = &g_hT[t & 1][0][dir][0][0];
                const size_t split_stride = (size_t)2 * BB * UU;
                #pragma unroll
                for (int hh = 0; hh < 2; hh++) {
                    #pragma unroll 4
                    for (int rep = 0; rep < 16; rep++) {
                        int idx = tid + NTHR * rep;
                        int row = idx >> 5, c = hh * 32 + (idx & 31);
                        int sp = row >> 6, br = row & 63;
                        const void* src = hp + (size_t)sp * split_stride + (size_t)br * UU + c * 8;
                        cpasync16(smA32 + row * 1024 + ((c ^ (row & 7)) << 4), src);
                    }
                    cp_commit();
                }
            }

            float D[2][2][4], D2[2][2][4];
            #pragma unroll
            for (int i = 0; i < 2; i++)
                #pragma unroll
                for (int j = 0; j < 2; j++)
                    #pragma unroll
                    for (int e = 0; e < 4; e++) { D[i][j][e] = 0.0f; D2[i][j][e] = 0.0f; }

            // phase A: K-half0 resident
            cp_wait1();
            __syncthreads();
            for (int q = qloA; q < qloA + qnA; q++) {
                uint32_t qo = (uint32_t)(q * 128);
                #pragma unroll
                for (int j = 0; j < 4; j++) {
                    uint32_t a0[4], a1[4], p0[4], p1[4];
                    ldm4(a0, aBase[0] + qo + aSw[0][j]);
                    ldm4(a1, aBase[1] + qo + aSw[1][j]);
                    ldm4(p0, bBase[0] + qo + bSw[0][j]);
                    ldm4(p1, bBase[1] + qo + bSw[1][j]);
                    mma16816(D[0][0],  a0, p0[0], p0[1]);
                    mma16816(D[0][1],  a0, p0[2], p0[3]);
                    mma16816(D2[0][0], a0, p1[0], p1[1]);
                    mma16816(D2[0][1], a0, p1[2], p1[3]);
                    mma16816(D[1][0],  a1, p0[0], p0[1]);
                    mma16816(D[1][1],  a1, p0[2], p0[3]);
                    mma16816(D2[1][0], a1, p1[0], p1[1]);
                    mma16816(D2[1][1], a1, p1[2], p1[3]);
                }
            }

            // phase B: K-half1 resident
            cp_wait0();
            __syncthreads();
            for (int q = qloB; q < qloB + qnB; q++) {
                uint32_t qo = (uint32_t)(q * 128);
                #pragma unroll
                for (int j = 0; j < 4; j++) {
                    uint32_t a0[4], a1[4], p0[4], p1[4];
                    ldm4(a0, aBase[0] + qo + aSw[0][j]);
                    ldm4(a1, aBase[1] + qo + aSw[1][j]);
                    ldm4(p0, bBase[0] + qo + bSw[0][j]);
                    ldm4(p1, bBase[1] + qo + bSw[1][j]);
                    mma16816(D[0][0],  a0, p0[0], p0[1]);
                    mma16816(D[0][1],  a0, p0[2], p0[3]);
                    mma16816(D2[0][0], a0, p1[0], p1[1]);
                    mma16816(D2[0][1], a0, p1[2], p1[3]);
                    mma16816(D[1][0],  a1, p0[0], p0[1]);
                    mma16816(D[1][1],  a1, p0[2], p0[3]);
                    mma16816(D2[1][0], a1, p1[0], p1[1]);
                    mma16816(D2[1][1], a1, p1[2], p1[3]);
                }
            }

            // z store (R10 layout)
            {
                int g = lane >> 2, tq = lane & 3;
                #pragma unroll
                for (int mt = 0; mt < 2; mt++) {
                    int r0_ = zrow + mt * 16 + g;
                    int cc = zcol + 2 * tq;
                    *(float2*)(zst + r0_ * ZS2 + cc)            = make_float2(D[mt][0][0], D[mt][0][1]);
                    *(float2*)(zst + r0_ * ZS2 + cc + 8)        = make_float2(D[mt][1][0], D[mt][1][1]);
                    *(float2*)(zst + r0_ * ZS2 + cc + 16)       = make_float2(D2[mt][0][0], D2[mt][0][1]);
                    *(float2*)(zst + r0_ * ZS2 + cc + 24)       = make_float2(D2[mt][1][0], D2[mt][1][1]);
                    *(float2*)(zst + (r0_ + 8) * ZS2 + cc)      = make_float2(D[mt][0][2], D[mt][0][3]);
                    *(float2*)(zst + (r0_ + 8) * ZS2 + cc + 8)  = make_float2(D[mt][1][2], D[mt][1][3]);
                    *(float2*)(zst + (r0_ + 8) * ZS2 + cc + 16) = make_float2(D2[mt][0][2], D2[mt][0][3]);
                    *(float2*)(zst + (r0_ + 8) * ZS2 + cc + 24) = make_float2(D2[mt][1][2], D2[mt][1][3]);
                }
            }
        }
        __syncthreads();

        {   // cell update: z = Q0(hi@b + lo@64+b) + Q1(h0@b + h1@64+b) + Y
            #pragma unroll
            for (int cell = 0; cell < 2; cell++) {
                int du = du0 + 4 * cell;
                float zg4[4];
                #pragma unroll
                for (int g = 0; g < 4; g++) {
                    int lc = g * 8 + du;
                    zg4[g] = zst[b * ZS2 + lc] + zst[(64 + b) * ZS2 + lc]
                           + zst[b * ZS2 + 32 + lc] + zst[(64 + b) * ZS2 + 32 + lc]
                           + yv[cell * 4 + g];
                }
                float cn = sigm(zg4[1]) * creg[cell] + sigm(zg4[0]) * tanhf(zg4[2]);
                float hn = sigm(zg4[3]) * tanhf(cn);
                creg[cell] = cn;
                __nv_bfloat16 hi = __float2bfloat16(hn);
                __nv_bfloat16 lo = __float2bfloat16(hn - __bfloat162float(hi));
                hstage[(0 * 64 + b) * 8 + du] = hi;
                hstage[(1 * 64 + b) * 8 + du] = lo;
            }
        }
        __syncthreads();

        if (tid < 128) {
            int sp = tid >> 6, br = tid & 63;
            uint4 v = *(const uint4*)(hstage + (sp * 64 + br) * 8);
            *(uint4*)(&g_hT[(t + 1) & 1][sp][dir][br][u0]) = v;
        }

        if (t < TT - 1) {
            __threadfence();
            __syncthreads();
            if (tid == 0) *(volatile unsigned*)&g_flag[dir][cta][0] = (unsigned)(t + 1);
        }
    }

    // final all-arrive barrier, then flag reset for graph replay
    __threadfence();
    __syncthreads();
    if (tid == 0) {
        volatile unsigned* gen = &g_gen[dir][0];
        unsigned g = *gen;
        unsigned a = atomicAdd(&g_cnt[dir][0], 1u);
        if (a == 63) {
            g_cnt[dir][0] = 0;
            __threadfence();
            *gen = g + 1;
        } else {
            while (*gen == g) {}
        }
        g_flag[dir][cta][0] = 0;
    }
}

// -------- head --------
__global__ __launch_bounds__(256) void k_head(
    const float* __restrict__ W1, const float* __restrict__ b1,
    const float* __restrict__ W2, const float* __restrict__ b2,
    float* __restrict__ out)
{
    int b = blockIdx.x;
    int tid = threadIdx.x;
    int j = tid & 63, kq = tid >> 6;
    float s = 0.0f;
    for (int k = kq * 256; k < kq * 256 + 256; k++) {
        int dir = k >> 9, u = k & 511;
        float hv = __bfloat162float(g_hT[0][0][dir][b][u]) +
                   __bfloat162float(g_hT[0][1][dir][b][u]);
        s += hv * W1[(size_t)k * 64 + j];
    }
    __shared__ float red[4][64];
    red[kq][j] = s;
    __syncthreads();
    if (tid < 64) {
        float sj = red[0][j] + red[1][j] + red[2][j] + red[3][j] + b1[j];
        red[0][j] = sj * W2[j];
    }
    __syncthreads();
    if (tid == 0) {
        float v = 0.0f;
        #pragma unroll
        for (int q = 0; q < 64; q++) v += red[0][q];
        out[b] = sigm(v + b2[0]);
    }
}

extern "C" void kernel_launch(void* const* d_in, const int* in_sizes, int n_in,
                              void* d_out, int out_size)
{
    const int*   sent = (const int*)  d_in[0];
    const float* emb  = (const float*)d_in[1];
    const float* Wxf  = (const float*)d_in[2];
    const float* Whf  = (const float*)d_in[3];
    const float* bf   = (const float*)d_in[4];
    const float* Wxb  = (const float*)d_in[5];
    const float* Whb  = (const float*)d_in[6];
    const float* bbv  = (const float*)d_in[7];
    const float* W1   = (const float*)d_in[8];
    const float* b1   = (const float*)d_in[9];
    const float* W2   = (const float*)d_in[10];
    const float* b2   = (const float*)d_in[11];
    float* out = (float*)d_out;

    const int smem_rec = 131072 + 65536 + 128 * ZS2 * 4;   // 230400 B
    const int smem_xw  = 65536 + 131072;                   // 196608 B
    cudaFuncSetAttribute(k_rec, cudaFuncAttributeMaxDynamicSharedMemorySize, smem_rec);
    cudaFuncSetAttribute(k_xw2, cudaFuncAttributeMaxDynamicSharedMemorySize, smem_xw);

    k_prepw<<<4096, 256>>>(Wxf, Wxb);
    k_prepx<<<dim3(512, 4), 256>>>(sent, emb);
    k_xw2<<<512 * 32, 256, smem_xw>>>(bf, bbv);
    k_rec<<<NCTA, NTHR, smem_rec>>>(Whf, Whb);
    k_head<<<64, 256>>>(W1, b1, W2, b2, out);
}

// round 13
// speedup vs baseline: 1.3019x; 1.1295x over previous
#include <cuda_runtime.h>
#include <cuda_bf16.h>
#include <math.h>
#include <stdint.h>

#define TT   512
#define BB   64
#define EE   256
#define UU   512
#define G4U  2048
#define NCTA 128   // 64 per direction
#define NTHR 256
#define ZS2  66    // k_rec z stride (floats, even)

// -------- device scratch --------
__device__ __align__(16) float g_Y[(size_t)2 * TT * G4U * BB];   // [dir][t][n][b]
__device__ __align__(16) __nv_bfloat16 g_hT[2][2][2][BB][UU];    // [parity][split][dir][b][u]
__device__ __align__(16) __nv_bfloat16 g_X[TT][2][BB][EE];       // [t][split][b][e]
__device__ __align__(16) __nv_bfloat16 g_Wxb[2][2][G4U][EE];     // [dir][split][n][e]
__device__ unsigned g_flag[2][64][16];                           // 64B-spaced step flags
__device__ unsigned g_cnt[2][32];
__device__ unsigned g_gen[2][32];

__device__ __forceinline__ float sigm(float x) { return 1.0f / (1.0f + expf(-x)); }

__device__ __forceinline__ uint32_t smem_u32(const void* p) {
    uint32_t a;
    asm("{ .reg .u64 t; cvta.to.shared.u64 t, %1; cvt.u32.u64 %0, t; }" : "=r"(a) : "l"(p));
    return a;
}
__device__ __forceinline__ void ldm4(uint32_t* r, uint32_t addr) {
    asm volatile("ldmatrix.sync.aligned.m8n8.x4.shared.b16 {%0,%1,%2,%3}, [%4];"
                 : "=r"(r[0]), "=r"(r[1]), "=r"(r[2]), "=r"(r[3]) : "r"(addr));
}
__device__ __forceinline__ void mma16816(float* d, const uint32_t* a, uint32_t b0, uint32_t b1) {
    asm volatile("mma.sync.aligned.m16n8k16.row.col.f32.bf16.bf16.f32 "
                 "{%0,%1,%2,%3}, {%4,%5,%6,%7}, {%8,%9}, {%0,%1,%2,%3};"
                 : "+f"(d[0]), "+f"(d[1]), "+f"(d[2]), "+f"(d[3])
                 : "r"(a[0]), "r"(a[1]), "r"(a[2]), "r"(a[3]), "r"(b0), "r"(b1));
}
__device__ __forceinline__ void cpasync16(uint32_t dst, const void* src) {
    asm volatile("cp.async.cg.shared.global [%0], [%1], 16;" :: "r"(dst), "l"(src));
}
__device__ __forceinline__ void cp_commit() {
    asm volatile("cp.async.commit_group;");
}
__device__ __forceinline__ void cp_wait1() {
    asm volatile("cp.async.wait_group 1;" ::: "memory");
}
__device__ __forceinline__ void cp_wait0() {
    asm volatile("cp.async.wait_group 0;" ::: "memory");
}

// -------- prep: Wx -> bf16 hi/lo, n-major --------
__global__ __launch_bounds__(256) void k_prepw(const float* __restrict__ Wxf,
                                               const float* __restrict__ Wxb)
{
    int bid = blockIdx.x;
    int dir = bid >> 11, n = bid & 2047;
    const float* Wx = dir ? Wxb : Wxf;
    int e = threadIdx.x;
    float w = Wx[(size_t)e * G4U + n];
    __nv_bfloat16 hi = __float2bfloat16(w);
    __nv_bfloat16 lo = __float2bfloat16(w - __bfloat162float(hi));
    g_Wxb[dir][0][n][e] = hi;
    g_Wxb[dir][1][n][e] = lo;
}

// -------- prep: embedding gather -> bf16 hi/lo --------
__global__ __launch_bounds__(256) void k_prepx(const int* __restrict__ sent,
                                               const float* __restrict__ emb)
{
    int t = blockIdx.x;
    int b0 = blockIdx.y * 16;
    int tid = threadIdx.x;
    __shared__ int vrow[16];
    if (tid < 16) vrow[tid] = sent[(b0 + tid) * TT + t];
    __syncthreads();
    for (int j = 0; j < 16; j++) {
        int b = b0 + j;
        float v = emb[(size_t)vrow[j] * EE + tid];
        __nv_bfloat16 hi = __float2bfloat16(v);
        __nv_bfloat16 lo = __float2bfloat16(v - __bfloat162float(hi));
        g_X[t][0][b][tid] = hi;
        g_X[t][1][b][tid] = lo;
    }
}

// -------- input projection via HMMA (R10, unchanged; full precision) --------
__global__ __launch_bounds__(256) void k_xw2(const float* __restrict__ bf,
                                             const float* __restrict__ bbv)
{
    int bid = blockIdx.x;
    int t = bid >> 5;
    int r5 = bid & 31;
    int dir = r5 >> 4, ntile = r5 & 15;

    extern __shared__ char sm[];
    char* smA = sm;
    char* smB = sm + 65536;
    float* zst  = (float*)sm;
    float* zst2 = zst + 128 * 129;

    int tid = threadIdx.x, lane = tid & 31, w = tid >> 5;

    {
        const uint4* Xs = (const uint4*)&g_X[t][0][0][0];
        #pragma unroll
        for (int idx = tid; idx < 4096; idx += 256) {
            int row = idx >> 5, c = idx & 31;
            uint4 v = __ldcg(Xs + idx);
            *(uint4*)(smA + row * 512 + ((c ^ (row & 7)) << 4)) = v;
        }
    }
    {
        const uint4* Ws = (const uint4*)&g_Wxb[dir][0][0][0];
        #pragma unroll
        for (int idx = tid; idx < 8192; idx += 256) {
            int q = idx >> 5, c = idx & 31;
            int sp = q >> 7, nl = q & 127;
            uint4 v = __ldcg(Ws + ((size_t)sp * G4U + ntile * 128 + nl) * 32 + c);
            *(uint4*)(smB + q * 512 + ((c ^ (q & 7)) << 4)) = v;
        }
    }
    __syncthreads();

    uint32_t smA32 = smem_u32(smA), smB32 = smem_u32(smB);
    bool q0w = (w < 4);
    int mg   = q0w ? (w >> 1) : 0;
    int ng   = q0w ? (w & 1) : ((w - 4) >> 1);
    int half = q0w ? 0 : ((w - 4) & 1);
    int arows = mg * 64;
    int brows = (q0w ? 0 : 128) + ng * 64;
    int jlo = half * 8;
    int jn  = q0w ? 16 : 8;

    float D[4][8][4];
    {
        uint32_t aBase[4]; int ar7[4];
        uint32_t bBase[4]; int br7[4];
        int dA = (lane >> 4) & 1, dB = (lane >> 3) & 1;
        #pragma unroll
        for (int mi = 0; mi < 4; mi++) {
            int row = arows + mi * 16 + ((lane >> 3) & 1) * 8 + (lane & 7);
            aBase[mi] = smA32 + row * 512;
            ar7[mi] = row & 7;
        }
        #pragma unroll
        for (int nt = 0; nt < 4; nt++) {
            int row = brows + nt * 16 + ((lane >> 4) & 1) * 8 + (lane & 7);
            bBase[nt] = smB32 + row * 512;
            br7[nt] = row & 7;
        }
        #pragma unroll
        for (int mi = 0; mi < 4; mi++)
            #pragma unroll
            for (int nj = 0; nj < 8; nj++)
                #pragma unroll
                for (int e = 0; e < 4; e++) D[mi][nj][e] = 0.0f;

        #pragma unroll 2
        for (int j = jlo; j < jlo + jn; j++) {
            uint32_t af[4][4], bb[4][4];
            #pragma unroll
            for (int mi = 0; mi < 4; mi++)
                ldm4(af[mi], aBase[mi] + ((((2 * j + dA) ^ ar7[mi])) << 4));
            #pragma unroll
            for (int nt = 0; nt < 4; nt++)
                ldm4(bb[nt], bBase[nt] + ((((2 * j + dB) ^ br7[nt])) << 4));
            #pragma unroll
            for (int mi = 0; mi < 4; mi++)
                #pragma unroll
                for (int nt = 0; nt < 4; nt++) {
                    mma16816(D[mi][2 * nt + 0], af[mi], bb[nt][0], bb[nt][1]);
                    mma16816(D[mi][2 * nt + 1], af[mi], bb[nt][2], bb[nt][3]);
                }
        }
    }
    __syncthreads();

    {
        int g = lane >> 2, tq = lane & 3;
        float* dst = q0w ? zst : zst2;
        int zrb = q0w ? arows : half * 64;
        #pragma unroll
        for (int mi = 0; mi < 4; mi++)
            #pragma unroll
            for (int nj = 0; nj < 8; nj++) {
                int r = zrb + mi * 16 + g;
                int c = ng * 64 + nj * 8 + 2 * tq;
                dst[r * 129 + c]           = D[mi][nj][0];
                dst[r * 129 + c + 1]       = D[mi][nj][1];
                dst[(r + 8) * 129 + c]     = D[mi][nj][2];
                dst[(r + 8) * 129 + c + 1] = D[mi][nj][3];
            }
    }
    __syncthreads();

    {
        const float* bias = dir ? bbv : bf;
        float* Y = g_Y + ((size_t)dir * TT + t) * (size_t)(G4U * BB)
                       + (size_t)ntile * 128 * BB;
        #pragma unroll
        for (int rep = 0; rep < 8; rep++) {
            int task = tid + 256 * rep;
            int n = task >> 4, b4 = (task & 15) << 2;
            float bn = bias[ntile * 128 + n];
            float4 o;
            o.x = zst[(b4 + 0) * 129 + n] + zst[(b4 + 64) * 129 + n]
                + zst2[(b4 + 0) * 129 + n] + zst2[(b4 + 64) * 129 + n] + bn;
            o.y = zst[(b4 + 1) * 129 + n] + zst[(b4 + 65) * 129 + n]
                + zst2[(b4 + 1) * 129 + n] + zst2[(b4 + 65) * 129 + n] + bn;
            o.z = zst[(b4 + 2) * 129 + n] + zst[(b4 + 66) * 129 + n]
                + zst2[(b4 + 2) * 129 + n] + zst2[(b4 + 66) * 129 + n] + bn;
            o.w = zst[(b4 + 3) * 129 + n] + zst[(b4 + 67) * 129 + n]
                + zst2[(b4 + 3) * 129 + n] + zst2[(b4 + 67) * 129 + n] + bn;
            *(float4*)(Y + (size_t)n * BB + b4) = o;
        }
    }
}

// -------- persistent HMMA recurrence: z = (h_hi + h_lo) . W_hi, 2-group pipeline --------
// Deliberate precision trade: the h_hi*W_lo correction (~2^-9 rel) is dropped;
// measured-rel-err budget ~3e-6 vs 1e-3 threshold.
// w_i (i 0-3):  A m-block i x W_hi, K-half0 (phase A) -> zst[rows][0..31]
// w_{i+4}:      A m-block i x W_hi, K-half1 (phase B) -> zst[rows][32..63]
__global__ __launch_bounds__(NTHR, 1) void k_rec(
    const float* __restrict__ Whf, const float* __restrict__ Whb)
{
    extern __shared__ char dsm[];
    char* smA  = dsm;                        // 131072 B
    char* smB  = dsm + 131072;               // 32768 B (W_hi only)
    float* zst = (float*)(dsm + 131072 + 32768);   // [128][ZS2]
    __nv_bfloat16* hstage = (__nv_bfloat16*)smA;

    int tid = threadIdx.x, lane = tid & 31, w = tid >> 5;
    int dir = blockIdx.x >> 6;
    int cta = blockIdx.x & 63;
    int u0  = cta * 8;
    const float* Wh = dir ? Whb : Whf;

    // B build (once): 32 rows of W_hi
    for (int idx = tid; idx < 32 * 512; idx += NTHR) {
        int n = idx >> 9, k = idx & 511;
        float wv = Wh[(size_t)k * G4U + ((n >> 3) * UU + u0 + (n & 7))];
        __nv_bfloat16 hi = __float2bfloat16(wv);
        uint32_t off = (uint32_t)(n * 1024 + ((((k >> 3) ^ (n & 7))) << 4) + (k & 7) * 2);
        *(__nv_bfloat16*)(smB + off) = hi;
    }
    for (int i = tid; i < 128 * ZS2; i += NTHR) zst[i] = 0.0f;

    // warp tiling: m-block = w&3, K-half = w>>2 (phase A = half0, B = half1)
    uint32_t smA32 = smem_u32(smA), smB32 = smem_u32(smB);
    bool phA = (w < 4);
    int arow = (w & 3) * 32;
    int zcol = phA ? 0 : 32;
    int qlo  = phA ? 0 : 4;

    uint32_t aBase[2], bBase[2], aSw[2][4], bSw[2][4];
    {
        int dA = (lane >> 4) & 1;
        #pragma unroll
        for (int mt = 0; mt < 2; mt++) {
            int row = arow + mt * 16 + ((lane >> 3) & 1) * 8 + (lane & 7);
            aBase[mt] = smA32 + row * 1024;
            #pragma unroll
            for (int j = 0; j < 4; j++)
                aSw[mt][j] = (uint32_t)(((2 * j + dA) ^ (row & 7)) << 4);
        }
        int dB = (lane >> 3) & 1;
        #pragma unroll
        for (int nt = 0; nt < 2; nt++) {
            int row = nt * 16 + ((lane >> 4) & 1) * 8 + (lane & 7);
            bBase[nt] = smB32 + row * 1024;
            #pragma unroll
            for (int j = 0; j < 4; j++)
                bSw[nt][j] = (uint32_t)(((2 * j + dB) ^ (row & 7)) << 4);
        }
    }

    int b = tid & 63, du0 = tid >> 6;
    float creg[2] = {0.0f, 0.0f};
    const float* Ybase = g_Y + (size_t)dir * TT * (size_t)(G4U * BB);
    __syncthreads();

    for (int t = 0; t < TT; t++) {
        int ttv = dir ? (TT - 1 - t) : t;
        const float* Yt = Ybase + (size_t)ttv * (size_t)(G4U * BB);
        float yv[8];
        #pragma unroll
        for (int g = 0; g < 4; g++) {
            yv[g]     = __ldcg(Yt + (size_t)(g * UU + u0 + du0) * BB + b);
            yv[4 + g] = __ldcg(Yt + (size_t)(g * UU + u0 + du0 + 4) * BB + b);
        }

        if (t > 0) {
            // barrier wait for producers of h(t)
            if (tid < 64) {
                while (*(volatile unsigned*)&g_flag[dir][tid][0] < (unsigned)t) {}
            }
            __syncthreads();

            // A build via cp.async: 2 K-half groups
            {
                const __nv_bfloat16* hp = &g_hT[t & 1][0][dir][0][0];
                const size_t split_stride = (size_t)2 * BB * UU;
                #pragma unroll
                for (int hh = 0; hh < 2; hh++) {
                    #pragma unroll 4
                    for (int rep = 0; rep < 16; rep++) {
                        int idx = tid + NTHR * rep;
                        int row = idx >> 5, c = hh * 32 + (idx & 31);
                        int sp = row >> 6, br = row & 63;
                        const void* src = hp + (size_t)sp * split_stride + (size_t)br * UU + c * 8;
                        cpasync16(smA32 + row * 1024 + ((c ^ (row & 7)) << 4), src);
                    }
                    cp_commit();
                }
            }

            float D[2][4][4];
            #pragma unroll
            for (int mt = 0; mt < 2; mt++)
                #pragma unroll
                for (int nj = 0; nj < 4; nj++)
                    #pragma unroll
                    for (int e = 0; e < 4; e++) D[mt][nj][e] = 0.0f;

            // phase A: K-half0 resident -> warps 0-3 compute
            cp_wait1();
            __syncthreads();
            if (phA) {
                for (int q = 0; q < 4; q++) {
                    uint32_t qo = (uint32_t)(q * 128);
                    #pragma unroll
                    for (int j = 0; j < 4; j++) {
                        uint32_t a0[4], a1[4], p0[4], p1[4];
                        ldm4(a0, aBase[0] + qo + aSw[0][j]);
                        ldm4(a1, aBase[1] + qo + aSw[1][j]);
                        ldm4(p0, bBase[0] + qo + bSw[0][j]);
                        ldm4(p1, bBase[1] + qo + bSw[1][j]);
                        mma16816(D[0][0], a0, p0[0], p0[1]);
                        mma16816(D[0][1], a0, p0[2], p0[3]);
                        mma16816(D[0][2], a0, p1[0], p1[1]);
                        mma16816(D[0][3], a0, p1[2], p1[3]);
                        mma16816(D[1][0], a1, p0[0], p0[1]);
                        mma16816(D[1][1], a1, p0[2], p0[3]);
                        mma16816(D[1][2], a1, p1[0], p1[1]);
                        mma16816(D[1][3], a1, p1[2], p1[3]);
                    }
                }
            }

            // phase B: K-half1 resident -> warps 4-7 compute
            cp_wait0();
            __syncthreads();
            if (!phA) {
                for (int q = 4; q < 8; q++) {
                    uint32_t qo = (uint32_t)(q * 128);
                    #pragma unroll
                    for (int j = 0; j < 4; j++) {
                        uint32_t a0[4], a1[4], p0[4], p1[4];
                        ldm4(a0, aBase[0] + qo + aSw[0][j]);
                        ldm4(a1, aBase[1] + qo + aSw[1][j]);
                        ldm4(p0, bBase[0] + qo + bSw[0][j]);
                        ldm4(p1, bBase[1] + qo + bSw[1][j]);
                        mma16816(D[0][0], a0, p0[0], p0[1]);
                        mma16816(D[0][1], a0, p0[2], p0[3]);
                        mma16816(D[0][2], a0, p1[0], p1[1]);
                        mma16816(D[0][3], a0, p1[2], p1[3]);
                        mma16816(D[1][0], a1, p0[0], p0[1]);
                        mma16816(D[1][1], a1, p0[2], p0[3]);
                        mma16816(D[1][2], a1, p1[0], p1[1]);
                        mma16816(D[1][3], a1, p1[2], p1[3]);
                    }
                }
            }

            // z store: warp's m32n32 K-half partial at [arow..][zcol..]
            {
                int g = lane >> 2, tq = lane & 3;
                #pragma unroll
                for (int mt = 0; mt < 2; mt++) {
                    int r0_ = arow + mt * 16 + g;
                    int cc = zcol + 2 * tq;
                    #pragma unroll
                    for (int nj = 0; nj < 4; nj++) {
                        *(float2*)(zst + r0_ * ZS2 + cc + nj * 8) =
                            make_float2(D[mt][nj][0], D[mt][nj][1]);
                        *(float2*)(zst + (r0_ + 8) * ZS2 + cc + nj * 8) =
                            make_float2(D[mt][nj][2], D[mt][nj][3]);
                    }
                }
            }
        }
        __syncthreads();

        {   // cell update: z = (hi@b + lo@64+b) over K-half0 + K-half1 planes + Y
            #pragma unroll
            for (int cell = 0; cell < 2; cell++) {
                int du = du0 + 4 * cell;
                float zg4[4];
                #pragma unroll
                for (int g = 0; g < 4; g++) {
                    int lc = g * 8 + du;
                    zg4[g] = zst[b * ZS2 + lc] + zst[(64 + b) * ZS2 + lc]
                           + zst[b * ZS2 + 32 + lc] + zst[(64 + b) * ZS2 + 32 + lc]
                           + yv[cell * 4 + g];
                }
                float cn = sigm(zg4[1]) * creg[cell] + sigm(zg4[0]) * tanhf(zg4[2]);
                float hn = sigm(zg4[3]) * tanhf(cn);
                creg[cell] = cn;
                __nv_bfloat16 hi = __float2bfloat16(hn);
                __nv_bfloat16 lo = __float2bfloat16(hn - __bfloat162float(hi));
                hstage[(0 * 64 + b) * 8 + du] = hi;
                hstage[(1 * 64 + b) * 8 + du] = lo;
            }
        }
        __syncthreads();

        if (tid < 128) {
            int sp = tid >> 6, br = tid & 63;
            uint4 v = *(const uint4*)(hstage + (sp * 64 + br) * 8);
            *(uint4*)(&g_hT[(t + 1) & 1][sp][dir][br][u0]) = v;
        }

        if (t < TT - 1) {
            __threadfence();
            __syncthreads();
            if (tid == 0) *(volatile unsigned*)&g_flag[dir][cta][0] = (unsigned)(t + 1);
        }
    }

    // final all-arrive barrier, then flag reset for graph replay
    __threadfence();
    __syncthreads();
    if (tid == 0) {
        volatile unsigned* gen = &g_gen[dir][0];
        unsigned g = *gen;
        unsigned a = atomicAdd(&g_cnt[dir][0], 1u);
        if (a == 63) {
            g_cnt[dir][0] = 0;
            __threadfence();
            *gen = g + 1;
        } else {
            while (*gen == g) {}
        }
        g_flag[dir][cta][0] = 0;
    }
}

// -------- head --------
__global__ __launch_bounds__(256) void k_head(
    const float* __restrict__ W1, const float* __restrict__ b1,
    const float* __restrict__ W2, const float* __restrict__ b2,
    float* __restrict__ out)
{
    int b = blockIdx.x;
    int tid = threadIdx.x;
    int j = tid & 63, kq = tid >> 6;
    float s = 0.0f;
    for (int k = kq * 256; k < kq * 256 + 256; k++) {
        int dir = k >> 9, u = k & 511;
        float hv = __bfloat162float(g_hT[0][0][dir][b][u]) +
                   __bfloat162float(g_hT[0][1][dir][b][u]);
        s += hv * W1[(size_t)k * 64 + j];
    }
    __shared__ float red[4][64];
    red[kq][j] = s;
    __syncthreads();
    if (tid < 64) {
        float sj = red[0][j] + red[1][j] + red[2][j] + red[3][j] + b1[j];
        red[0][j] = sj * W2[j];
    }
    __syncthreads();
    if (tid == 0) {
        float v = 0.0f;
        #pragma unroll
        for (int q = 0; q < 64; q++) v += red[0][q];
        out[b] = sigm(v + b2[0]);
    }
}

extern "C" void kernel_launch(void* const* d_in, const int* in_sizes, int n_in,
                              void* d_out, int out_size)
{
    const int*   sent = (const int*)  d_in[0];
    const float* emb  = (const float*)d_in[1];
    const float* Wxf  = (const float*)d_in[2];
    const float* Whf  = (const float*)d_in[3];
    const float* bf   = (const float*)d_in[4];
    const float* Wxb  = (const float*)d_in[5];
    const float* Whb  = (const float*)d_in[6];
    const float* bbv  = (const float*)d_in[7];
    const float* W1   = (const float*)d_in[8];
    const float* b1   = (const float*)d_in[9];
    const float* W2   = (const float*)d_in[10];
    const float* b2   = (const float*)d_in[11];
    float* out = (float*)d_out;

    const int smem_rec = 131072 + 32768 + 128 * ZS2 * 4;   // 197632 B
    const int smem_xw  = 65536 + 131072;                   // 196608 B
    cudaFuncSetAttribute(k_rec, cudaFuncAttributeMaxDynamicSharedMemorySize, smem_rec);
    cudaFuncSetAttribute(k_xw2, cudaFuncAttributeMaxDynamicSharedMemorySize, smem_xw);

    k_prepw<<<4096, 256>>>(Wxf, Wxb);
    k_prepx<<<dim3(512, 4), 256>>>(sent, emb);
    k_xw2<<<512 * 32, 256, smem_xw>>>(bf, bbv);
    k_rec<<<NCTA, NTHR, smem_rec>>>(Whf, Whb);
    k_head<<<64, 256>>>(W1, b1, W2, b2, out);
}

// round 14
// speedup vs baseline: 1.4907x; 1.1450x over previous
#include <cuda_runtime.h>
#include <cuda_bf16.h>
#include <math.h>
#include <stdint.h>

#define TT   512
#define BB   64
#define EE   256
#define UU   512
#define G4U  2048
#define NCTA 128   // 64 per direction
#define NTHR 256
#define ZS2  66    // k_rec z stride (floats, even)

// -------- device scratch --------
__device__ __align__(16) float g_Y[(size_t)2 * TT * G4U * BB];   // [dir][t][n][b]
__device__ __align__(16) __nv_bfloat16 g_hT[2][2][2][BB][UU];    // [parity][split][dir][b][u]
__device__ __align__(16) __nv_bfloat16 g_X[TT][2][BB][EE];       // [t][split][b][e]
__device__ __align__(16) __nv_bfloat16 g_Wxb[2][G4U][EE];        // [dir][n][e]  (hi only)
__device__ unsigned g_flag[2][64][16];                           // 64B-spaced step flags
__device__ unsigned g_cnt[2][32];
__device__ unsigned g_gen[2][32];

// fast transcendentals (ex2.approx-based; saturate correctly at +-inf)
__device__ __forceinline__ float fsigm(float x) {
    return __fdividef(1.0f, 1.0f + __expf(-x));
}
__device__ __forceinline__ float ftanh(float x) {
    return __fdividef(2.0f, 1.0f + __expf(-2.0f * x)) - 1.0f;
}

__device__ __forceinline__ uint32_t smem_u32(const void* p) {
    uint32_t a;
    asm("{ .reg .u64 t; cvta.to.shared.u64 t, %1; cvt.u32.u64 %0, t; }" : "=r"(a) : "l"(p));
    return a;
}
__device__ __forceinline__ void ldm4(uint32_t* r, uint32_t addr) {
    asm volatile("ldmatrix.sync.aligned.m8n8.x4.shared.b16 {%0,%1,%2,%3}, [%4];"
                 : "=r"(r[0]), "=r"(r[1]), "=r"(r[2]), "=r"(r[3]) : "r"(addr));
}
__device__ __forceinline__ void mma16816(float* d, const uint32_t* a, uint32_t b0, uint32_t b1) {
    asm volatile("mma.sync.aligned.m16n8k16.row.col.f32.bf16.bf16.f32 "
                 "{%0,%1,%2,%3}, {%4,%5,%6,%7}, {%8,%9}, {%0,%1,%2,%3};"
                 : "+f"(d[0]), "+f"(d[1]), "+f"(d[2]), "+f"(d[3])
                 : "r"(a[0]), "r"(a[1]), "r"(a[2]), "r"(a[3]), "r"(b0), "r"(b1));
}
__device__ __forceinline__ void cpasync16(uint32_t dst, const void* src) {
    asm volatile("cp.async.cg.shared.global [%0], [%1], 16;" :: "r"(dst), "l"(src));
}
__device__ __forceinline__ void cp_commit_wait0() {
    asm volatile("cp.async.commit_group;");
    asm volatile("cp.async.wait_group 0;" ::: "memory");
}

// -------- prep: Wx -> bf16 hi, n-major --------
__global__ __launch_bounds__(256) void k_prepw(const float* __restrict__ Wxf,
                                               const float* __restrict__ Wxb)
{
    int bid = blockIdx.x;
    int dir = bid >> 11, n = bid & 2047;
    const float* Wx = dir ? Wxb : Wxf;
    int e = threadIdx.x;
    float w = Wx[(size_t)e * G4U + n];
    g_Wxb[dir][n][e] = __float2bfloat16(w);
}

// -------- prep: embedding gather -> bf16 hi/lo --------
__global__ __launch_bounds__(256) void k_prepx(const int* __restrict__ sent,
                                               const float* __restrict__ emb)
{
    int t = blockIdx.x;
    int b0 = blockIdx.y * 16;
    int tid = threadIdx.x;
    __shared__ int vrow[16];
    if (tid < 16) vrow[tid] = sent[(b0 + tid) * TT + t];
    __syncthreads();
    for (int j = 0; j < 16; j++) {
        int b = b0 + j;
        float v = emb[(size_t)vrow[j] * EE + tid];
        __nv_bfloat16 hi = __float2bfloat16(v);
        __nv_bfloat16 lo = __float2bfloat16(v - __bfloat162float(hi));
        g_X[t][0][b][tid] = hi;
        g_X[t][1][b][tid] = lo;
    }
}

// -------- input projection via HMMA: Y = (x_hi + x_lo) . W_hi, 8 balanced warps --------
// A[128 x 256] = [x_hi(64b); x_lo(64b)]; B[128 x 256] = W_hi
// warp w: m-block (w&3)*32, n-half (w>>2)*64, full K (16 j-iters)
__global__ __launch_bounds__(256) void k_xw2(const float* __restrict__ bf,
                                             const float* __restrict__ bbv)
{
    int bid = blockIdx.x;
    int t = bid >> 5;
    int r5 = bid & 31;
    int dir = r5 >> 4, ntile = r5 & 15;

    extern __shared__ char sm[];
    char* smA = sm;                  // 128 rows x 512B = 64 KB
    char* smB = sm + 65536;          // 128 rows x 512B = 64 KB
    float* zst = (float*)sm;         // [128][129] (66 KB), reuse after MMA

    int tid = threadIdx.x, lane = tid & 31, w = tid >> 5;

    {
        const uint4* Xs = (const uint4*)&g_X[t][0][0][0];
        #pragma unroll
        for (int idx = tid; idx < 4096; idx += 256) {
            int row = idx >> 5, c = idx & 31;
            uint4 v = __ldcg(Xs + idx);
            *(uint4*)(smA + row * 512 + ((c ^ (row & 7)) << 4)) = v;
        }
    }
    {
        const uint4* Ws = (const uint4*)&g_Wxb[dir][0][0];
        #pragma unroll
        for (int idx = tid; idx < 4096; idx += 256) {
            int q = idx >> 5, c = idx & 31;
            uint4 v = __ldcg(Ws + ((size_t)(ntile * 128 + q)) * 32 + c);
            *(uint4*)(smB + q * 512 + ((c ^ (q & 7)) << 4)) = v;
        }
    }
    __syncthreads();

    uint32_t smA32 = smem_u32(smA), smB32 = smem_u32(smB);
    int arows = (w & 3) * 32;
    int brows = (w >> 2) * 64;

    float D[2][8][4];
    {
        uint32_t aBase[2]; int ar7[2];
        uint32_t bBase[4]; int br7[4];
        int dA = (lane >> 4) & 1, dB = (lane >> 3) & 1;
        #pragma unroll
        for (int mi = 0; mi < 2; mi++) {
            int row = arows + mi * 16 + ((lane >> 3) & 1) * 8 + (lane & 7);
            aBase[mi] = smA32 + row * 512;
            ar7[mi] = row & 7;
        }
        #pragma unroll
        for (int nt = 0; nt < 4; nt++) {
            int row = brows + nt * 16 + ((lane >> 4) & 1) * 8 + (lane & 7);
            bBase[nt] = smB32 + row * 512;
            br7[nt] = row & 7;
        }
        #pragma unroll
        for (int mi = 0; mi < 2; mi++)
            #pragma unroll
            for (int nj = 0; nj < 8; nj++)
                #pragma unroll
                for (int e = 0; e < 4; e++) D[mi][nj][e] = 0.0f;

        #pragma unroll 2
        for (int j = 0; j < 16; j++) {
            uint32_t af[2][4], bb[4][4];
            #pragma unroll
            for (int mi = 0; mi < 2; mi++)
                ldm4(af[mi], aBase[mi] + ((((2 * j + dA) ^ ar7[mi])) << 4));
            #pragma unroll
            for (int nt = 0; nt < 4; nt++)
                ldm4(bb[nt], bBase[nt] + ((((2 * j + dB) ^ br7[nt])) << 4));
            #pragma unroll
            for (int mi = 0; mi < 2; mi++)
                #pragma unroll
                for (int nt = 0; nt < 4; nt++) {
                    mma16816(D[mi][2 * nt + 0], af[mi], bb[nt][0], bb[nt][1]);
                    mma16816(D[mi][2 * nt + 1], af[mi], bb[nt][2], bb[nt][3]);
                }
        }
    }
    __syncthreads();

    {
        int g = lane >> 2, tq = lane & 3;
        #pragma unroll
        for (int mi = 0; mi < 2; mi++)
            #pragma unroll
            for (int nj = 0; nj < 8; nj++) {
                int r = arows + mi * 16 + g;
                int c = brows + nj * 8 + 2 * tq;
                zst[r * 129 + c]           = D[mi][nj][0];
                zst[r * 129 + c + 1]       = D[mi][nj][1];
                zst[(r + 8) * 129 + c]     = D[mi][nj][2];
                zst[(r + 8) * 129 + c + 1] = D[mi][nj][3];
            }
    }
    __syncthreads();

    {
        const float* bias = dir ? bbv : bf;
        float* Y = g_Y + ((size_t)dir * TT + t) * (size_t)(G4U * BB)
                       + (size_t)ntile * 128 * BB;
        #pragma unroll
        for (int rep = 0; rep < 8; rep++) {
            int task = tid + 256 * rep;
            int n = task >> 4, b4 = (task & 15) << 2;
            float bn = bias[ntile * 128 + n];
            float4 o;
            o.x = zst[(b4 + 0) * 129 + n] + zst[(b4 + 64) * 129 + n] + bn;
            o.y = zst[(b4 + 1) * 129 + n] + zst[(b4 + 65) * 129 + n] + bn;
            o.z = zst[(b4 + 2) * 129 + n] + zst[(b4 + 66) * 129 + n] + bn;
            o.w = zst[(b4 + 3) * 129 + n] + zst[(b4 + 67) * 129 + n] + bn;
            *(float4*)(Y + (size_t)n * BB + b4) = o;
        }
    }
}

// -------- persistent HMMA recurrence: z = (h_hi + h_lo) . W_hi, 8 concurrent warps --------
// warp w: m-block (w&3)*32 rows of A, K-half (w>>2) -> zst[rows][(w>>2)*32 ..]
__global__ __launch_bounds__(NTHR, 1) void k_rec(
    const float* __restrict__ Whf, const float* __restrict__ Whb)
{
    extern __shared__ char dsm[];
    char* smA  = dsm;                        // 131072 B
    char* smB  = dsm + 131072;               // 32768 B (W_hi only)
    float* zst = (float*)(dsm + 131072 + 32768);   // [128][ZS2]
    __nv_bfloat16* hstage = (__nv_bfloat16*)smA;

    int tid = threadIdx.x, lane = tid & 31, w = tid >> 5;
    int dir = blockIdx.x >> 6;
    int cta = blockIdx.x & 63;
    int u0  = cta * 8;
    const float* Wh = dir ? Whb : Whf;

    // B build (once): 32 rows of W_hi
    for (int idx = tid; idx < 32 * 512; idx += NTHR) {
        int n = idx >> 9, k = idx & 511;
        float wv = Wh[(size_t)k * G4U + ((n >> 3) * UU + u0 + (n & 7))];
        __nv_bfloat16 hi = __float2bfloat16(wv);
        uint32_t off = (uint32_t)(n * 1024 + ((((k >> 3) ^ (n & 7))) << 4) + (k & 7) * 2);
        *(__nv_bfloat16*)(smB + off) = hi;
    }
    for (int i = tid; i < 128 * ZS2; i += NTHR) zst[i] = 0.0f;

    // warp tiling: m-block = w&3, K-half = w>>2 (all warps concurrent)
    uint32_t smA32 = smem_u32(smA), smB32 = smem_u32(smB);
    int arow = (w & 3) * 32;
    int kh   = w >> 2;
    int zcol = kh * 32;
    int qlo  = kh * 4;

    uint32_t aBase[2], bBase[2], aSw[2][4], bSw[2][4];
    {
        int dA = (lane >> 4) & 1;
        #pragma unroll
        for (int mt = 0; mt < 2; mt++) {
            int row = arow + mt * 16 + ((lane >> 3) & 1) * 8 + (lane & 7);
            aBase[mt] = smA32 + row * 1024;
            #pragma unroll
            for (int j = 0; j < 4; j++)
                aSw[mt][j] = (uint32_t)(((2 * j + dA) ^ (row & 7)) << 4);
        }
        int dB = (lane >> 3) & 1;
        #pragma unroll
        for (int nt = 0; nt < 2; nt++) {
            int row = nt * 16 + ((lane >> 4) & 1) * 8 + (lane & 7);
            bBase[nt] = smB32 + row * 1024;
            #pragma unroll
            for (int j = 0; j < 4; j++)
                bSw[nt][j] = (uint32_t)(((2 * j + dB) ^ (row & 7)) << 4);
        }
    }

    int b = tid & 63, du0 = tid >> 6;
    float creg[2] = {0.0f, 0.0f};
    const float* Ybase = g_Y + (size_t)dir * TT * (size_t)(G4U * BB);
    __syncthreads();

    for (int t = 0; t < TT; t++) {
        int ttv = dir ? (TT - 1 - t) : t;
        const float* Yt = Ybase + (size_t)ttv * (size_t)(G4U * BB);
        float yv[8];
        #pragma unroll
        for (int g = 0; g < 4; g++) {
            yv[g]     = __ldcg(Yt + (size_t)(g * UU + u0 + du0) * BB + b);
            yv[4 + g] = __ldcg(Yt + (size_t)(g * UU + u0 + du0 + 4) * BB + b);
        }

        if (t > 0) {
            // barrier wait for producers of h(t)
            if (tid < 64) {
                while (*(volatile unsigned*)&g_flag[dir][tid][0] < (unsigned)t) {}
            }
            __syncthreads();

            // A build via cp.async (single group)
            {
                const __nv_bfloat16* hp = &g_hT[t & 1][0][dir][0][0];
                const size_t split_stride = (size_t)2 * BB * UU;
                #pragma unroll 8
                for (int rep = 0; rep < 32; rep++) {
                    int idx = tid + NTHR * rep;
                    int row = idx >> 6, c = idx & 63;
                    int sp = row >> 6, br = row & 63;
                    const void* src = hp + (size_t)sp * split_stride + (size_t)br * UU + c * 8;
                    cpasync16(smA32 + row * 1024 + ((c ^ (row & 7)) << 4), src);
                }
                cp_commit_wait0();
            }
            __syncthreads();

            float D[2][4][4];
            #pragma unroll
            for (int mt = 0; mt < 2; mt++)
                #pragma unroll
                for (int nj = 0; nj < 4; nj++)
                    #pragma unroll
                    for (int e = 0; e < 4; e++) D[mt][nj][e] = 0.0f;

            // all 8 warps concurrent: 4 K-chunks each
            for (int q = qlo; q < qlo + 4; q++) {
                uint32_t qo = (uint32_t)(q * 128);
                #pragma unroll
                for (int j = 0; j < 4; j++) {
                    uint32_t a0[4], a1[4], p0[4], p1[4];
                    ldm4(a0, aBase[0] + qo + aSw[0][j]);
                    ldm4(a1, aBase[1] + qo + aSw[1][j]);
                    ldm4(p0, bBase[0] + qo + bSw[0][j]);
                    ldm4(p1, bBase[1] + qo + bSw[1][j]);
                    mma16816(D[0][0], a0, p0[0], p0[1]);
                    mma16816(D[0][1], a0, p0[2], p0[3]);
                    mma16816(D[0][2], a0, p1[0], p1[1]);
                    mma16816(D[0][3], a0, p1[2], p1[3]);
                    mma16816(D[1][0], a1, p0[0], p0[1]);
                    mma16816(D[1][1], a1, p0[2], p0[3]);
                    mma16816(D[1][2], a1, p1[0], p1[1]);
                    mma16816(D[1][3], a1, p1[2], p1[3]);
                }
            }

            // z store: warp's m32n32 K-half partial at [arow..][zcol..]
            {
                int g = lane >> 2, tq = lane & 3;
                #pragma unroll
                for (int mt = 0; mt < 2; mt++) {
                    int r0_ = arow + mt * 16 + g;
                    int cc = zcol + 2 * tq;
                    #pragma unroll
                    for (int nj = 0; nj < 4; nj++) {
                        *(float2*)(zst + r0_ * ZS2 + cc + nj * 8) =
                            make_float2(D[mt][nj][0], D[mt][nj][1]);
                        *(float2*)(zst + (r0_ + 8) * ZS2 + cc + nj * 8) =
                            make_float2(D[mt][nj][2], D[mt][nj][3]);
                    }
                }
            }
        }
        __syncthreads();

        {   // cell update: z = (hi@b + lo@64+b) over both K-half planes + Y
            #pragma unroll
            for (int cell = 0; cell < 2; cell++) {
                int du = du0 + 4 * cell;
                float zg4[4];
                #pragma unroll
                for (int g = 0; g < 4; g++) {
                    int lc = g * 8 + du;
                    zg4[g] = zst[b * ZS2 + lc] + zst[(64 + b) * ZS2 + lc]
                           + zst[b * ZS2 + 32 + lc] + zst[(64 + b) * ZS2 + 32 + lc]
                           + yv[cell * 4 + g];
                }
                float cn = fsigm(zg4[1]) * creg[cell] + fsigm(zg4[0]) * ftanh(zg4[2]);
                float hn = fsigm(zg4[3]) * ftanh(cn);
                creg[cell] = cn;
                __nv_bfloat16 hi = __float2bfloat16(hn);
                __nv_bfloat16 lo = __float2bfloat16(hn - __bfloat162float(hi));
                hstage[(0 * 64 + b) * 8 + du] = hi;
                hstage[(1 * 64 + b) * 8 + du] = lo;
            }
        }
        __syncthreads();

        if (tid < 128) {
            int sp = tid >> 6, br = tid & 63;
            uint4 v = *(const uint4*)(hstage + (sp * 64 + br) * 8);
            *(uint4*)(&g_hT[(t + 1) & 1][sp][dir][br][u0]) = v;
        }

        if (t < TT - 1) {
            __threadfence();
            __syncthreads();
            if (tid == 0) *(volatile unsigned*)&g_flag[dir][cta][0] = (unsigned)(t + 1);
        }
    }

    // final all-arrive barrier, then flag reset for graph replay
    __threadfence();
    __syncthreads();
    if (tid == 0) {
        volatile unsigned* gen = &g_gen[dir][0];
        unsigned g = *gen;
        unsigned a = atomicAdd(&g_cnt[dir][0], 1u);
        if (a == 63) {
            g_cnt[dir][0] = 0;
            __threadfence();
            *gen = g + 1;
        } else {
            while (*gen == g) {}
        }
        g_flag[dir][cta][0] = 0;
    }
}

// -------- head --------
__global__ __launch_bounds__(256) void k_head(
    const float* __restrict__ W1, const float* __restrict__ b1,
    const float* __restrict__ W2, const float* __restrict__ b2,
    float* __restrict__ out)
{
    int b = blockIdx.x;
    int tid = threadIdx.x;
    int j = tid & 63, kq = tid >> 6;
    float s = 0.0f;
    for (int k = kq * 256; k < kq * 256 + 256; k++) {
        int dir = k >> 9, u = k & 511;
        float hv = __bfloat162float(g_hT[0][0][dir][b][u]) +
                   __bfloat162float(g_hT[0][1][dir][b][u]);
        s += hv * W1[(size_t)k * 64 + j];
    }
    __shared__ float red[4][64];
    red[kq][j] = s;
    __syncthreads();
    if (tid < 64) {
        float sj = red[0][j] + red[1][j] + red[2][j] + red[3][j] + b1[j];
        red[0][j] = sj * W2[j];
    }
    __syncthreads();
    if (tid == 0) {
        float v = 0.0f;
        #pragma unroll
        for (int q = 0; q < 64; q++) v += red[0][q];
        out[b] = fsigm(v + b2[0]);
    }
}

extern "C" void kernel_launch(void* const* d_in, const int* in_sizes, int n_in,
                              void* d_out, int out_size)
{
    const int*   sent = (const int*)  d_in[0];
    const float* emb  = (const float*)d_in[1];
    const float* Wxf  = (const float*)d_in[2];
    const float* Whf  = (const float*)d_in[3];
    const float* bf   = (const float*)d_in[4];
    const float* Wxb  = (const float*)d_in[5];
    const float* Whb  = (const float*)d_in[6];
    const float* bbv  = (const float*)d_in[7];
    const float* W1   = (const float*)d_in[8];
    const float* b1   = (const float*)d_in[9];
    const float* W2   = (const float*)d_in[10];
    const float* b2   = (const float*)d_in[11];
    float* out = (float*)d_out;

    const int smem_rec = 131072 + 32768 + 128 * ZS2 * 4;   // 197632 B
    const int smem_xw  = 131072;                           // max(A+B, zst)
    cudaFuncSetAttribute(k_rec, cudaFuncAttributeMaxDynamicSharedMemorySize, smem_rec);
    cudaFuncSetAttribute(k_xw2, cudaFuncAttributeMaxDynamicSharedMemorySize, smem_xw);

    k_prepw<<<4096, 256>>>(Wxf, Wxb);
    k_prepx<<<dim3(512, 4), 256>>>(sent, emb);
    k_xw2<<<512 * 32, 256, smem_xw>>>(bf, bbv);
    k_rec<<<NCTA, NTHR, smem_rec>>>(Whf, Whb);
    k_head<<<64, 256>>>(W1, b1, W2, b2, out);
}

// round 15
// speedup vs baseline: 1.5886x; 1.0656x over previous
#include <cuda_runtime.h>
#include <cuda_bf16.h>
#include <math.h>
#include <stdint.h>

#define TT   512
#define BB   64
#define EE   256
#define UU   512
#define G4U  2048
#define NCTA 128   // 64 per direction
#define NTHR 256
#define ZS2  66    // k_rec z stride (floats, even)

// -------- device scratch --------
__device__ __align__(16) float g_Y[(size_t)2 * TT * G4U * BB];   // [dir][t][n][b]
// h as a pre-swizzled A-tile image: [parity][dir][131072 bytes]
// row = split*64 + b (128 rows x 1024 B); chunk c (16B) at row*1024 + ((c^(row&7))<<4)
__device__ __align__(128) char g_hA[2][2][131072];
__device__ __align__(16) __nv_bfloat16 g_X[TT][2][BB][EE];       // [t][split][b][e]
__device__ __align__(16) __nv_bfloat16 g_Wxb[2][G4U][EE];        // [dir][n][e]  (hi only)
__device__ unsigned g_flag[2][64][16];                           // 64B-spaced step flags
__device__ unsigned g_cnt[2][32];
__device__ unsigned g_gen[2][32];

// fast transcendentals (ex2.approx-based; saturate correctly at +-inf)
__device__ __forceinline__ float fsigm(float x) {
    return __fdividef(1.0f, 1.0f + __expf(-x));
}
__device__ __forceinline__ float ftanh(float x) {
    return __fdividef(2.0f, 1.0f + __expf(-2.0f * x)) - 1.0f;
}

__device__ __forceinline__ uint32_t smem_u32(const void* p) {
    uint32_t a;
    asm("{ .reg .u64 t; cvta.to.shared.u64 t, %1; cvt.u32.u64 %0, t; }" : "=r"(a) : "l"(p));
    return a;
}
__device__ __forceinline__ void ldm4(uint32_t* r, uint32_t addr) {
    asm volatile("ldmatrix.sync.aligned.m8n8.x4.shared.b16 {%0,%1,%2,%3}, [%4];"
                 : "=r"(r[0]), "=r"(r[1]), "=r"(r[2]), "=r"(r[3]) : "r"(addr));
}
__device__ __forceinline__ void mma16816(float* d, const uint32_t* a, uint32_t b0, uint32_t b1) {
    asm volatile("mma.sync.aligned.m16n8k16.row.col.f32.bf16.bf16.f32 "
                 "{%0,%1,%2,%3}, {%4,%5,%6,%7}, {%8,%9}, {%0,%1,%2,%3};"
                 : "+f"(d[0]), "+f"(d[1]), "+f"(d[2]), "+f"(d[3])
                 : "r"(a[0]), "r"(a[1]), "r"(a[2]), "r"(a[3]), "r"(b0), "r"(b1));
}
#define MBAR_INIT(a, c) \
    asm volatile("mbarrier.init.shared.b64 [%0], %1;" :: "r"(a), "r"((uint32_t)(c)) : "memory")
#define MBAR_EXPECT_TX(a, n) \
    asm volatile("mbarrier.arrive.expect_tx.shared.b64 _, [%0], %1;" :: "r"(a), "r"((uint32_t)(n)) : "memory")
#define MBAR_WAIT(a, ph) do {                                               \
    asm volatile("{ .reg .pred P1; WL%=:\n\t"                               \
        "mbarrier.try_wait.parity.acquire.cta.shared::cta.b64 P1, [%0], %1, 0x989680;\n\t" \
        "@P1 bra.uni WD%=;\n\t bra.uni WL%=;\n\t WD%=: }"                   \
        :: "r"(a), "r"((uint32_t)(ph)) : "memory");                         \
} while (0)
__device__ __forceinline__ void bulk_cp(uint32_t dst, const void* src, uint32_t bytes, uint32_t mbar) {
    asm volatile("cp.async.bulk.shared::cta.global.mbarrier::complete_tx::bytes [%0], [%1], %2, [%3];"
                 :: "r"(dst), "l"(src), "r"(bytes), "r"(mbar) : "memory");
}

// -------- prep: Wx -> bf16 hi, n-major --------
__global__ __launch_bounds__(256) void k_prepw(const float* __restrict__ Wxf,
                                               const float* __restrict__ Wxb)
{
    int bid = blockIdx.x;
    int dir = bid >> 11, n = bid & 2047;
    const float* Wx = dir ? Wxb : Wxf;
    int e = threadIdx.x;
    float w = Wx[(size_t)e * G4U + n];
    g_Wxb[dir][n][e] = __float2bfloat16(w);
}

// -------- prep: embedding gather -> bf16 hi/lo --------
__global__ __launch_bounds__(256) void k_prepx(const int* __restrict__ sent,
                                               const float* __restrict__ emb)
{
    int t = blockIdx.x;
    int b0 = blockIdx.y * 16;
    int tid = threadIdx.x;
    __shared__ int vrow[16];
    if (tid < 16) vrow[tid] = sent[(b0 + tid) * TT + t];
    __syncthreads();
    for (int j = 0; j < 16; j++) {
        int b = b0 + j;
        float v = emb[(size_t)vrow[j] * EE + tid];
        __nv_bfloat16 hi = __float2bfloat16(v);
        __nv_bfloat16 lo = __float2bfloat16(v - __bfloat162float(hi));
        g_X[t][0][b][tid] = hi;
        g_X[t][1][b][tid] = lo;
    }
}

// -------- input projection via HMMA (R14, unchanged) --------
__global__ __launch_bounds__(256) void k_xw2(const float* __restrict__ bf,
                                             const float* __restrict__ bbv)
{
    int bid = blockIdx.x;
    int t = bid >> 5;
    int r5 = bid & 31;
    int dir = r5 >> 4, ntile = r5 & 15;

    extern __shared__ char sm[];
    char* smA = sm;
    char* smB = sm + 65536;
    float* zst = (float*)sm;

    int tid = threadIdx.x, lane = tid & 31, w = tid >> 5;

    {
        const uint4* Xs = (const uint4*)&g_X[t][0][0][0];
        #pragma unroll
        for (int idx = tid; idx < 4096; idx += 256) {
            int row = idx >> 5, c = idx & 31;
            uint4 v = __ldcg(Xs + idx);
            *(uint4*)(smA + row * 512 + ((c ^ (row & 7)) << 4)) = v;
        }
    }
    {
        const uint4* Ws = (const uint4*)&g_Wxb[dir][0][0];
        #pragma unroll
        for (int idx = tid; idx < 4096; idx += 256) {
            int q = idx >> 5, c = idx & 31;
            uint4 v = __ldcg(Ws + ((size_t)(ntile * 128 + q)) * 32 + c);
            *(uint4*)(smB + q * 512 + ((c ^ (q & 7)) << 4)) = v;
        }
    }
    __syncthreads();

    uint32_t smA32 = smem_u32(smA), smB32 = smem_u32(smB);
    int arows = (w & 3) * 32;
    int brows = (w >> 2) * 64;

    float D[2][8][4];
    {
        uint32_t aBase[2]; int ar7[2];
        uint32_t bBase[4]; int br7[4];
        int dA = (lane >> 4) & 1, dB = (lane >> 3) & 1;
        #pragma unroll
        for (int mi = 0; mi < 2; mi++) {
            int row = arows + mi * 16 + ((lane >> 3) & 1) * 8 + (lane & 7);
            aBase[mi] = smA32 + row * 512;
            ar7[mi] = row & 7;
        }
        #pragma unroll
        for (int nt = 0; nt < 4; nt++) {
            int row = brows + nt * 16 + ((lane >> 4) & 1) * 8 + (lane & 7);
            bBase[nt] = smB32 + row * 512;
            br7[nt] = row & 7;
        }
        #pragma unroll
        for (int mi = 0; mi < 2; mi++)
            #pragma unroll
            for (int nj = 0; nj < 8; nj++)
                #pragma unroll
                for (int e = 0; e < 4; e++) D[mi][nj][e] = 0.0f;

        #pragma unroll 2
        for (int j = 0; j < 16; j++) {
            uint32_t af[2][4], bb[4][4];
            #pragma unroll
            for (int mi = 0; mi < 2; mi++)
                ldm4(af[mi], aBase[mi] + ((((2 * j + dA) ^ ar7[mi])) << 4));
            #pragma unroll
            for (int nt = 0; nt < 4; nt++)
                ldm4(bb[nt], bBase[nt] + ((((2 * j + dB) ^ br7[nt])) << 4));
            #pragma unroll
            for (int mi = 0; mi < 2; mi++)
                #pragma unroll
                for (int nt = 0; nt < 4; nt++) {
                    mma16816(D[mi][2 * nt + 0], af[mi], bb[nt][0], bb[nt][1]);
                    mma16816(D[mi][2 * nt + 1], af[mi], bb[nt][2], bb[nt][3]);
                }
        }
    }
    __syncthreads();

    {
        int g = lane >> 2, tq = lane & 3;
        #pragma unroll
        for (int mi = 0; mi < 2; mi++)
            #pragma unroll
            for (int nj = 0; nj < 8; nj++) {
                int r = arows + mi * 16 + g;
                int c = brows + nj * 8 + 2 * tq;
                zst[r * 129 + c]           = D[mi][nj][0];
                zst[r * 129 + c + 1]       = D[mi][nj][1];
                zst[(r + 8) * 129 + c]     = D[mi][nj][2];
                zst[(r + 8) * 129 + c + 1] = D[mi][nj][3];
            }
    }
    __syncthreads();

    {
        const float* bias = dir ? bbv : bf;
        float* Y = g_Y + ((size_t)dir * TT + t) * (size_t)(G4U * BB)
                       + (size_t)ntile * 128 * BB;
        #pragma unroll
        for (int rep = 0; rep < 8; rep++) {
            int task = tid + 256 * rep;
            int n = task >> 4, b4 = (task & 15) << 2;
            float bn = bias[ntile * 128 + n];
            float4 o;
            o.x = zst[(b4 + 0) * 129 + n] + zst[(b4 + 64) * 129 + n] + bn;
            o.y = zst[(b4 + 1) * 129 + n] + zst[(b4 + 65) * 129 + n] + bn;
            o.z = zst[(b4 + 2) * 129 + n] + zst[(b4 + 66) * 129 + n] + bn;
            o.w = zst[(b4 + 3) * 129 + n] + zst[(b4 + 67) * 129 + n] + bn;
            *(float4*)(Y + (size_t)n * BB + b4) = o;
        }
    }
}

// -------- persistent HMMA recurrence: bulk-copy A image + 8 concurrent warps --------
__global__ __launch_bounds__(NTHR, 1) void k_rec(
    const float* __restrict__ Whf, const float* __restrict__ Whb)
{
    extern __shared__ char dsm[];
    char* smA  = dsm;                        // 131072 B (A image, same layout as g_hA)
    char* smB  = dsm + 131072;               // 32768 B (W_hi)
    float* zst = (float*)(dsm + 131072 + 32768);   // [128][ZS2]
    __nv_bfloat16* hstage = (__nv_bfloat16*)smA;
    __shared__ __align__(8) unsigned long long s_mbar[4];

    int tid = threadIdx.x, lane = tid & 31, w = tid >> 5;
    int dir = blockIdx.x >> 6;
    int cta = blockIdx.x & 63;
    int u0  = cta * 8;
    const float* Wh = dir ? Whb : Whf;

    uint32_t mbar0 = smem_u32(&s_mbar[0]);
    if (tid < 4) MBAR_INIT(mbar0 + tid * 8, 1);

    // B build (once): 32 rows of W_hi
    for (int idx = tid; idx < 32 * 512; idx += NTHR) {
        int n = idx >> 9, k = idx & 511;
        float wv = Wh[(size_t)k * G4U + ((n >> 3) * UU + u0 + (n & 7))];
        __nv_bfloat16 hi = __float2bfloat16(wv);
        uint32_t off = (uint32_t)(n * 1024 + ((((k >> 3) ^ (n & 7))) << 4) + (k & 7) * 2);
        *(__nv_bfloat16*)(smB + off) = hi;
    }
    for (int i = tid; i < 128 * ZS2; i += NTHR) zst[i] = 0.0f;

    // warp tiling: m-block = w&3 (rows (w&3)*32..+32), K-half = w>>2
    uint32_t smA32 = smem_u32(smA), smB32 = smem_u32(smB);
    int arow = (w & 3) * 32;
    int kh   = w >> 2;
    int zcol = kh * 32;
    int qlo  = kh * 4;
    uint32_t mymbar = mbar0 + (w & 3) * 8;

    uint32_t aBase[2], bBase[2], aSw[2][4], bSw[2][4];
    {
        int dA = (lane >> 4) & 1;
        #pragma unroll
        for (int mt = 0; mt < 2; mt++) {
            int row = arow + mt * 16 + ((lane >> 3) & 1) * 8 + (lane & 7);
            aBase[mt] = smA32 + row * 1024;
            #pragma unroll
            for (int j = 0; j < 4; j++)
                aSw[mt][j] = (uint32_t)(((2 * j + dA) ^ (row & 7)) << 4);
        }
        int dB = (lane >> 3) & 1;
        #pragma unroll
        for (int nt = 0; nt < 2; nt++) {
            int row = nt * 16 + ((lane >> 4) & 1) * 8 + (lane & 7);
            bBase[nt] = smB32 + row * 1024;
            #pragma unroll
            for (int j = 0; j < 4; j++)
                bSw[nt][j] = (uint32_t)(((2 * j + dB) ^ (row & 7)) << 4);
        }
    }

    int b = tid & 63, du0 = tid >> 6;
    float creg[2] = {0.0f, 0.0f};
    const float* Ybase = g_Y + (size_t)dir * TT * (size_t)(G4U * BB);
    int ph = 0;
    __syncthreads();

    for (int t = 0; t < TT; t++) {
        int ttv = dir ? (TT - 1 - t) : t;
        const float* Yt = Ybase + (size_t)ttv * (size_t)(G4U * BB);
        float yv[8];
        #pragma unroll
        for (int g = 0; g < 4; g++) {
            yv[g]     = __ldcg(Yt + (size_t)(g * UU + u0 + du0) * BB + b);
            yv[4 + g] = __ldcg(Yt + (size_t)(g * UU + u0 + du0 + 4) * BB + b);
        }

        if (t > 0) {
            // barrier wait for producers of h(t)
            if (tid < 64) {
                while (*(volatile unsigned*)&g_flag[dir][tid][0] < (unsigned)t) {}
            }
            __syncthreads();

            // A image bulk copy: 4 x 32 KB (rows blk*32..), per-block mbarrier
            if (tid < 4) {
                const char* src = &g_hA[t & 1][dir][0] + tid * 32768;
                MBAR_EXPECT_TX(mbar0 + tid * 8, 32768);
                bulk_cp(smA32 + tid * 32768, src, 32768, mbar0 + tid * 8);
            }
            MBAR_WAIT(mymbar, ph);

            float D[2][4][4];
            #pragma unroll
            for (int mt = 0; mt < 2; mt++)
                #pragma unroll
                for (int nj = 0; nj < 4; nj++)
                    #pragma unroll
                    for (int e = 0; e < 4; e++) D[mt][nj][e] = 0.0f;

            for (int q = qlo; q < qlo + 4; q++) {
                uint32_t qo = (uint32_t)(q * 128);
                #pragma unroll
                for (int j = 0; j < 4; j++) {
                    uint32_t a0[4], a1[4], p0[4], p1[4];
                    ldm4(a0, aBase[0] + qo + aSw[0][j]);
                    ldm4(a1, aBase[1] + qo + aSw[1][j]);
                    ldm4(p0, bBase[0] + qo + bSw[0][j]);
                    ldm4(p1, bBase[1] + qo + bSw[1][j]);
                    mma16816(D[0][0], a0, p0[0], p0[1]);
                    mma16816(D[0][1], a0, p0[2], p0[3]);
                    mma16816(D[0][2], a0, p1[0], p1[1]);
                    mma16816(D[0][3], a0, p1[2], p1[3]);
                    mma16816(D[1][0], a1, p0[0], p0[1]);
                    mma16816(D[1][1], a1, p0[2], p0[3]);
                    mma16816(D[1][2], a1, p1[0], p1[1]);
                    mma16816(D[1][3], a1, p1[2], p1[3]);
                }
            }
            ph ^= 1;

            // z store: warp's m32n32 K-half partial at [arow..][zcol..]
            {
                int g = lane >> 2, tq = lane & 3;
                #pragma unroll
                for (int mt = 0; mt < 2; mt++) {
                    int r0_ = arow + mt * 16 + g;
                    int cc = zcol + 2 * tq;
                    #pragma unroll
                    for (int nj = 0; nj < 4; nj++) {
                        *(float2*)(zst + r0_ * ZS2 + cc + nj * 8) =
                            make_float2(D[mt][nj][0], D[mt][nj][1]);
                        *(float2*)(zst + (r0_ + 8) * ZS2 + cc + nj * 8) =
                            make_float2(D[mt][nj][2], D[mt][nj][3]);
                    }
                }
            }
        }
        __syncthreads();

        {   // cell update: z = (hi@b + lo@64+b) over both K-half planes + Y
            #pragma unroll
            for (int cell = 0; cell < 2; cell++) {
                int du = du0 + 4 * cell;
                float zg4[4];
                #pragma unroll
                for (int g = 0; g < 4; g++) {
                    int lc = g * 8 + du;
                    zg4[g] = zst[b * ZS2 + lc] + zst[(64 + b) * ZS2 + lc]
                           + zst[b * ZS2 + 32 + lc] + zst[(64 + b) * ZS2 + 32 + lc]
                           + yv[cell * 4 + g];
                }
                float cn = fsigm(zg4[1]) * creg[cell] + fsigm(zg4[0]) * ftanh(zg4[2]);
                float hn = fsigm(zg4[3]) * ftanh(cn);
                creg[cell] = cn;
                __nv_bfloat16 hi = __float2bfloat16(hn);
                __nv_bfloat16 lo = __float2bfloat16(hn - __bfloat162float(hi));
                hstage[(0 * 64 + b) * 8 + du] = hi;
                hstage[(1 * 64 + b) * 8 + du] = lo;
            }
        }
        __syncthreads();

        // h' write into the pre-swizzled A image: row = sp*64+b, chunk = cta
        if (tid < 128) {
            int sp = tid >> 6, br = tid & 63;
            int row = sp * 64 + br;
            uint4 v = *(const uint4*)(hstage + (sp * 64 + br) * 8);
            char* dst = &g_hA[(t + 1) & 1][dir][0]
                      + row * 1024 + ((cta ^ (row & 7)) << 4);
            *(uint4*)dst = v;
        }

        if (t < TT - 1) {
            __threadfence();
            __syncthreads();
            if (tid == 0) *(volatile unsigned*)&g_flag[dir][cta][0] = (unsigned)(t + 1);
        }
    }

    // final all-arrive barrier, then flag reset for graph replay
    __threadfence();
    __syncthreads();
    if (tid == 0) {
        volatile unsigned* gen = &g_gen[dir][0];
        unsigned g = *gen;
        unsigned a = atomicAdd(&g_cnt[dir][0], 1u);
        if (a == 63) {
            g_cnt[dir][0] = 0;
            __threadfence();
            *gen = g + 1;
        } else {
            while (*gen == g) {}
        }
        g_flag[dir][cta][0] = 0;
    }
}

// -------- head (reads the parity-0 A image) --------
__global__ __launch_bounds__(256) void k_head(
    const float* __restrict__ W1, const float* __restrict__ b1,
    const float* __restrict__ W2, const float* __restrict__ b2,
    float* __restrict__ out)
{
    int b = blockIdx.x;
    int tid = threadIdx.x;
    int j = tid & 63, kq = tid >> 6;
    float s = 0.0f;
    for (int k = kq * 256; k < kq * 256 + 256; k++) {
        int dir = k >> 9, u = k & 511;
        const char* img = &g_hA[0][dir][0];
        int rh = b, rl = 64 + b;
        float hv =
            __bfloat162float(*(const __nv_bfloat16*)(img + rh * 1024 + ((((u >> 3) ^ (rh & 7))) << 4) + (u & 7) * 2)) +
            __bfloat162float(*(const __nv_bfloat16*)(img + rl * 1024 + ((((u >> 3) ^ (rl & 7))) << 4) + (u & 7) * 2));
        s += hv * W1[(size_t)k * 64 + j];
    }
    __shared__ float red[4][64];
    red[kq][j] = s;
    __syncthreads();
    if (tid < 64) {
        float sj = red[0][j] + red[1][j] + red[2][j] + red[3][j] + b1[j];
        red[0][j] = sj * W2[j];
    }
    __syncthreads();
    if (tid == 0) {
        float v = 0.0f;
        #pragma unroll
        for (int q = 0; q < 64; q++) v += red[0][q];
        out[b] = fsigm(v + b2[0]);
    }
}

extern "C" void kernel_launch(void* const* d_in, const int* in_sizes, int n_in,
                              void* d_out, int out_size)
{
    const int*   sent = (const int*)  d_in[0];
    const float* emb  = (const float*)d_in[1];
    const float* Wxf  = (const float*)d_in[2];
    const float* Whf  = (const float*)d_in[3];
    const float* bf   = (const float*)d_in[4];
    const float* Wxb  = (const float*)d_in[5];
    const float* Whb  = (const float*)d_in[6];
    const float* bbv  = (const float*)d_in[7];
    const float* W1   = (const float*)d_in[8];
    const float* b1   = (const float*)d_in[9];
    const float* W2   = (const float*)d_in[10];
    const float* b2   = (const float*)d_in[11];
    float* out = (float*)d_out;

    const int smem_rec = 131072 + 32768 + 128 * ZS2 * 4;   // 197632 B
    const int smem_xw  = 131072;
    cudaFuncSetAttribute(k_rec, cudaFuncAttributeMaxDynamicSharedMemorySize, smem_rec);
    cudaFuncSetAttribute(k_xw2, cudaFuncAttributeMaxDynamicSharedMemorySize, smem_xw);

    k_prepw<<<4096, 256>>>(Wxf, Wxb);
    k_prepx<<<dim3(512, 4), 256>>>(sent, emb);
    k_xw2<<<512 * 32, 256, smem_xw>>>(bf, bbv);
    k_rec<<<NCTA, NTHR, smem_rec>>>(Whf, Whb);
    k_head<<<64, 256>>>(W1, b1, W2, b2, out);
}